// round 2
// baseline (speedup 1.0000x reference)
#include <cuda_runtime.h>
#include <math.h>

// B=16 T=128 S=128 V=32000 E=256 F=512 ; u=[attn;h] (1024), gates 4F=2048
__device__ float g_keys[2048 * 512];     // [b*128+s][e]
__device__ float g_Zp[128 * 2048 * 16];  // [t][c*16+nl][b]
__device__ float g_Wp[128 * 1024 * 16];  // [c][k][nl]
__device__ float g_ut[2][1024 * 16];     // u transposed [k][b], parity buffered
__device__ float g_h[16 * 512];
__device__ float g_c[16 * 512];
__device__ float g_ctx[16 * 512];
__device__ float g_attns[2048 * 512];    // [t*16+b][col]

__global__ void p0_init(const float* __restrict__ h0, const float* __restrict__ c0) {
    int idx = blockIdx.x * 256 + threadIdx.x;
    if (idx < 8192) {
        g_ut[0][idx] = 0.f;
        g_h[idx] = h0[idx];
        g_c[idx] = c0[idx];
        int b = idx >> 9, j = idx & 511;
        g_ut[0][(512 + j) * 16 + b] = h0[idx];
    }
}

// W'[k][n]: k<512 -> Wk[256+k][n] (attn rows), else Wr[k-512][n]
__global__ void p3_wperm(const float* __restrict__ Wk, const float* __restrict__ Wr) {
    int idx = blockIdx.x * 256 + threadIdx.x;  // 128*1024*16 = 2^21
    int nl = idx & 15, k = (idx >> 4) & 1023, c = idx >> 14;
    int n = (nl >> 2) * 512 + c * 4 + (nl & 3);
    g_Wp[idx] = (k < 512) ? Wk[(size_t)(256 + k) * 2048 + n]
                          : Wr[(size_t)(k - 512) * 2048 + n];
}

// 128x128x8 double-buffered SGEMM, 256 thr.
// MODE0: keys=memory@Wm (N=512,K=512)  MODE1: Zp=emb[tok]@Wk[:256]+b (N=2048,K=256)
// MODE2: out=attns@Wf+bf (N=32000,K=512)
template <int MODE>
__global__ __launch_bounds__(256, 2)
void sgemm_k(const float* __restrict__ A, const float* __restrict__ Bm,
             const float* __restrict__ bias, const int* __restrict__ tokens,
             float* __restrict__ Cout, int K) {
    const int N = (MODE == 0) ? 512 : (MODE == 1 ? 2048 : 32000);
    __shared__ float As[2][8][128], Bs[2][8][128];
    int tid = threadIdx.x, m0 = blockIdx.y * 128, n0 = blockIdx.x * 128;
    int lm = tid >> 1, lk = (tid & 1) * 4;
    const float* Arow;
    if (MODE == 1) {
        int m = m0 + lm;
        Arow = A + (size_t)tokens[(m & 15) * 128 + (m >> 4)] * K + lk;
    } else {
        Arow = ((MODE == 2) ? g_attns : A) + (size_t)(m0 + lm) * K + lk;
    }
    int bk = tid >> 5, bn = (tid & 31) * 4;
    const float* Bptr = Bm + (size_t)bk * N + n0 + bn;

    float acc[8][8];
#pragma unroll
    for (int i = 0; i < 8; i++)
#pragma unroll
        for (int j = 0; j < 8; j++) acc[i][j] = 0.f;

    {
        float4 a4 = *(const float4*)Arow;
        float4 b4 = *(const float4*)Bptr;
        As[0][lk][lm] = a4.x; As[0][lk + 1][lm] = a4.y;
        As[0][lk + 2][lm] = a4.z; As[0][lk + 3][lm] = a4.w;
        *(float4*)&Bs[0][bk][bn] = b4;
    }
    __syncthreads();

    int nst = K / 8, buf = 0, tx = tid & 15, ty = tid >> 4;
    for (int ks = 1; ks <= nst; ks++) {
        float4 na, nb;
        if (ks < nst) {
            na = *(const float4*)(Arow + ks * 8);
            nb = *(const float4*)(Bptr + (size_t)ks * 8 * N);
        }
#pragma unroll
        for (int kk = 0; kk < 8; kk++) {
            float a[8], b[8];
            *(float4*)&a[0] = *(const float4*)&As[buf][kk][ty * 4];
            *(float4*)&a[4] = *(const float4*)&As[buf][kk][64 + ty * 4];
            *(float4*)&b[0] = *(const float4*)&Bs[buf][kk][tx * 4];
            *(float4*)&b[4] = *(const float4*)&Bs[buf][kk][64 + tx * 4];
#pragma unroll
            for (int i = 0; i < 8; i++)
#pragma unroll
                for (int j = 0; j < 8; j++) acc[i][j] += a[i] * b[j];
        }
        if (ks < nst) {
            buf ^= 1;
            As[buf][lk][lm] = na.x; As[buf][lk + 1][lm] = na.y;
            As[buf][lk + 2][lm] = na.z; As[buf][lk + 3][lm] = na.w;
            *(float4*)&Bs[buf][bk][bn] = nb;
            __syncthreads();
        }
    }

#pragma unroll
    for (int i = 0; i < 8; i++) {
        int mrow = m0 + ((i < 4) ? (ty * 4 + i) : (64 + ty * 4 + i - 4));
#pragma unroll
        for (int jh = 0; jh < 2; jh++) {
            int ncol = n0 + jh * 64 + tx * 4;
            float4 v = make_float4(acc[i][jh * 4], acc[i][jh * 4 + 1],
                                   acc[i][jh * 4 + 2], acc[i][jh * 4 + 3]);
            if (MODE == 0) {
                *(float4*)(g_keys + (size_t)mrow * 512 + ncol) = v;
            } else if (MODE == 2) {
                float4 bb = *(const float4*)(bias + ncol);
                v.x += bb.x; v.y += bb.y; v.z += bb.z; v.w += bb.w;
                *(float4*)(Cout + ((size_t)(mrow & 15) * 128 + (mrow >> 4)) * 32000 + ncol) = v;
            } else {
#pragma unroll
                for (int jj = 0; jj < 4; jj++) {
                    int n = ncol + jj;
                    int nl2 = (n >> 9) * 4 + (n & 3);
                    g_Zp[((size_t)(mrow >> 4) * 2048 + ((n & 511) >> 2) * 16 + nl2) * 16 +
                         (mrow & 15)] = acc[i][jh * 4 + jj] + bias[n];
                }
            }
        }
    }
}

// K1: z = Zp[t] + u@W' ; LSTM update. CTA c -> cols c*4..c*4+3 in all 4 gates.
__global__ __launch_bounds__(256) void k1_gate(int t) {
    int c = blockIdx.x, tid = threadIdx.x;
    int rp = t & 1, wp_ = rp ^ 1;
    int nl = tid & 15, kc = tid >> 4;
    const float* wpt = g_Wp + ((size_t)c * 1024 + kc * 64) * 16 + nl;
    const float4* up = (const float4*)(g_ut[rp] + kc * 64 * 16);
    float acc[16];
#pragma unroll
    for (int i = 0; i < 16; i++) acc[i] = 0.f;
#pragma unroll 4
    for (int i = 0; i < 64; i++) {
        float w = wpt[i * 16];
        float4 u0 = up[i * 4], u1 = up[i * 4 + 1], u2 = up[i * 4 + 2], u3 = up[i * 4 + 3];
        acc[0] += w * u0.x; acc[1] += w * u0.y; acc[2] += w * u0.z; acc[3] += w * u0.w;
        acc[4] += w * u1.x; acc[5] += w * u1.y; acc[6] += w * u1.z; acc[7] += w * u1.w;
        acc[8] += w * u2.x; acc[9] += w * u2.y; acc[10] += w * u2.z; acc[11] += w * u2.w;
        acc[12] += w * u3.x; acc[13] += w * u3.y; acc[14] += w * u3.z; acc[15] += w * u3.w;
    }
    __shared__ float ps[16][16][16];
#pragma unroll
    for (int b = 0; b < 16; b++) ps[kc][nl][b] = acc[b];
    __syncthreads();
    int nlr = tid >> 4, br = tid & 15;
    float z = g_Zp[((size_t)t * 2048 + c * 16 + nlr) * 16 + br];
#pragma unroll
    for (int q = 0; q < 16; q++) z += ps[q][nlr][br];
    __shared__ float zsh[16][16];
    zsh[nlr][br] = z;
    __syncthreads();
    if (tid < 64) {
        int jl = tid & 3, b = tid >> 2, j = c * 4 + jl;
        float zi = zsh[jl][b], zf = zsh[4 + jl][b], zg = zsh[8 + jl][b], zo = zsh[12 + jl][b];
        float cc = g_c[b * 512 + j];
        float si = 1.f / (1.f + expf(-zi)), sf = 1.f / (1.f + expf(-zf));
        float so = 1.f / (1.f + expf(-zo));
        cc = sf * cc + si * tanhf(zg);
        float hh = so * tanhf(cc);
        g_c[b * 512 + j] = cc;
        g_h[b * 512 + j] = hh;
        g_ut[wp_][(512 + j) * 16 + b] = hh;
    }
}

// K2: scores + softmax + ctx, one CTA per batch.
__global__ __launch_bounds__(512) void k2_attn(const float* __restrict__ memory) {
    int b = blockIdx.x, tid = threadIdx.x;
    __shared__ float h_sh[512], w_sh[128], red[16], ctx_ps[4][512];
    h_sh[tid] = g_h[b * 512 + tid];
    __syncthreads();
    int s = tid >> 2, q = tid & 3;
    const float4* kp = (const float4*)(g_keys + ((size_t)b * 128 + s) * 512 + q * 128);
    const float* hp = h_sh + q * 128;
    float a = 0.f;
#pragma unroll 8
    for (int i = 0; i < 32; i++) {
        float4 kv = kp[i];
        a += kv.x * hp[i * 4] + kv.y * hp[i * 4 + 1] + kv.z * hp[i * 4 + 2] + kv.w * hp[i * 4 + 3];
    }
    a += __shfl_xor_sync(0xffffffffu, a, 1);
    a += __shfl_xor_sync(0xffffffffu, a, 2);
    if (q == 0) w_sh[s] = a;
    __syncthreads();
    float sc = (tid < 128) ? w_sh[tid] : -1e30f;
    float mx = sc;
#pragma unroll
    for (int o = 16; o >= 1; o >>= 1) mx = fmaxf(mx, __shfl_xor_sync(0xffffffffu, mx, o));
    if ((tid & 31) == 0) red[tid >> 5] = mx;
    __syncthreads();
    float gmx = fmaxf(fmaxf(red[0], red[1]), fmaxf(red[2], red[3]));
    __syncthreads();
    float e = (tid < 128) ? expf(sc - gmx) : 0.f;
    float sm = e;
#pragma unroll
    for (int o = 16; o >= 1; o >>= 1) sm += __shfl_xor_sync(0xffffffffu, sm, o);
    if ((tid & 31) == 0) red[tid >> 5] = sm;
    __syncthreads();
    float gsum = red[0] + red[1] + red[2] + red[3];
    if (tid < 128) w_sh[tid] = e / gsum;
    __syncthreads();
    int d4 = tid & 127, sq = tid >> 7;
    const float* mp = memory + ((size_t)b * 128 + sq * 32) * 512;
    float4 ca = make_float4(0.f, 0.f, 0.f, 0.f);
#pragma unroll 4
    for (int i = 0; i < 32; i++) {
        float w = w_sh[sq * 32 + i];
        float4 mv = *(const float4*)(mp + (size_t)i * 512 + d4 * 4);
        ca.x += w * mv.x; ca.y += w * mv.y; ca.z += w * mv.z; ca.w += w * mv.w;
    }
    *(float4*)&ctx_ps[sq][d4 * 4] = ca;
    __syncthreads();
    g_ctx[b * 512 + tid] = ctx_ps[0][tid] + ctx_ps[1][tid] + ctx_ps[2][tid] + ctx_ps[3][tid];
}

// K3: attn = [h;ctx]@Wa -> next u (attn half) + attns[t]
__global__ __launch_bounds__(256) void k3_proj(const float* __restrict__ Wa, int t) {
    int cblk = blockIdx.x, tid = threadIdx.x, wp_ = (t & 1) ^ 1;
    int b = tid & 15, kq = tid >> 4, col0 = cblk * 4;
    const float* upp = (kq < 8) ? (g_h + b * 512 + kq * 64) : (g_ctx + b * 512 + (kq - 8) * 64);
    const float* wap = Wa + (size_t)(kq * 64) * 512 + col0;
    float a0 = 0.f, a1 = 0.f, a2 = 0.f, a3 = 0.f;
#pragma unroll 4
    for (int i = 0; i < 64; i++) {
        float u = upp[i];
        float4 w4 = *(const float4*)(wap + (size_t)i * 512);
        a0 += u * w4.x; a1 += u * w4.y; a2 += u * w4.z; a3 += u * w4.w;
    }
    __shared__ float ps[16][4][16];
    ps[kq][0][b] = a0; ps[kq][1][b] = a1; ps[kq][2][b] = a2; ps[kq][3][b] = a3;
    __syncthreads();
    if (tid < 64) {
        int cl = tid >> 4, bb = tid & 15;
        float v = 0.f;
#pragma unroll
        for (int q = 0; q < 16; q++) v += ps[q][cl][bb];
        int col = col0 + cl;
        g_ut[wp_][col * 16 + bb] = v;
        g_attns[((size_t)t * 16 + bb) * 512 + col] = v;
    }
}

extern "C" void kernel_launch(void* const* d_in, const int* in_sizes, int n_in,
                              void* d_out, int out_size) {
    const int* tokens = (const int*)d_in[0];
    const float* memory = (const float*)d_in[1];
    const float* h0 = (const float*)d_in[2];
    const float* c0 = (const float*)d_in[3];
    const float* emb = (const float*)d_in[4];
    const float* Wk = (const float*)d_in[5];
    const float* Wr = (const float*)d_in[6];
    const float* bvec = (const float*)d_in[7];
    const float* Wm = (const float*)d_in[8];
    const float* Wa = (const float*)d_in[9];
    const float* Wf = (const float*)d_in[10];
    const float* bf = (const float*)d_in[11];
    float* out = (float*)d_out;

    p0_init<<<32, 256>>>(h0, c0);
    p3_wperm<<<8192, 256>>>(Wk, Wr);
    sgemm_k<0><<<dim3(4, 16), 256>>>(memory, Wm, nullptr, nullptr, nullptr, 512);
    sgemm_k<1><<<dim3(16, 16), 256>>>(emb, Wk, bvec, tokens, nullptr, 256);

    for (int t = 0; t < 128; t++) {
        k1_gate<<<128, 256>>>(t);
        k2_attn<<<16, 512>>>(memory);
        k3_proj<<<128, 256>>>(Wa, t);
    }

    sgemm_k<2><<<dim3(250, 16), 256>>>(nullptr, Wf, bf, nullptr, out, 512);
}

// round 4
// speedup vs baseline: 1.0792x; 1.0792x over previous
#include <cuda_runtime.h>
#include <cuda_bf16.h>
#include <math.h>
#include <stdint.h>

// B=16 T=128 S=128 V=32000 E=256 F=512 ; u=[attn;h] (1024), gates 4F=2048
__device__ float g_keys[2048 * 512];     // [b*128+s][e]
__device__ float g_Zp[128 * 2048 * 16];  // [t][c*16+nl][b]
__device__ float g_Wp[128 * 1024 * 16];  // [c][k][nl]
__device__ float g_ut[2][1024 * 16];     // u transposed [k][b], parity buffered
__device__ float g_h[16 * 512];
__device__ float g_c[16 * 512];
__device__ float g_ctx[16 * 512];
__device__ float g_attns[2048 * 512];    // [t*16+b][col]
// bf16 split operands for tensor-core vocab GEMM
__device__ __nv_bfloat16 g_Ahi[2048 * 512];
__device__ __nv_bfloat16 g_Alo[2048 * 512];
__device__ __nv_bfloat16 g_Bhi[32000 * 512];  // Wf^T : [v][k], K contiguous
__device__ __nv_bfloat16 g_Blo[32000 * 512];

#define SW128(o) ((o) ^ (((o) >> 3) & 0x70))

__device__ __forceinline__ uint32_t smem_u32(const void* p) {
    uint32_t a;
    asm("{ .reg .u64 t; cvta.to.shared.u64 t, %1; cvt.u32.u64 %0, t; }" : "=r"(a) : "l"(p));
    return a;
}

#define LDSM4(r0, r1, r2, r3, addr) \
    asm volatile("ldmatrix.sync.aligned.m8n8.x4.shared.b16 {%0,%1,%2,%3}, [%4];" \
                 : "=r"(r0), "=r"(r1), "=r"(r2), "=r"(r3) : "r"(addr))

#define MMA16816(d, a, b) \
    asm volatile("mma.sync.aligned.m16n8k16.row.col.f32.bf16.bf16.f32 " \
                 "{%0,%1,%2,%3}, {%4,%5,%6,%7}, {%8,%9}, {%0,%1,%2,%3};" \
                 : "+f"((d)[0]), "+f"((d)[1]), "+f"((d)[2]), "+f"((d)[3]) \
                 : "r"((a)[0]), "r"((a)[1]), "r"((a)[2]), "r"((a)[3]), \
                   "r"((b)[0]), "r"((b)[1]))

__global__ void p0_init(const float* __restrict__ h0, const float* __restrict__ c0) {
    int idx = blockIdx.x * 256 + threadIdx.x;
    if (idx < 8192) {
        g_ut[0][idx] = 0.f;
        g_h[idx] = h0[idx];
        g_c[idx] = c0[idx];
        int b = idx >> 9, j = idx & 511;
        g_ut[0][(512 + j) * 16 + b] = h0[idx];
    }
}

// W'[k][n]: k<512 -> Wk[256+k][n] (attn rows), else Wr[k-512][n]
__global__ void p3_wperm(const float* __restrict__ Wk, const float* __restrict__ Wr) {
    int idx = blockIdx.x * 256 + threadIdx.x;
    int nl = idx & 15, k = (idx >> 4) & 1023, c = idx >> 14;
    int n = (nl >> 2) * 512 + c * 4 + (nl & 3);
    g_Wp[idx] = (k < 512) ? Wk[(size_t)(256 + k) * 2048 + n]
                          : Wr[(size_t)(k - 512) * 2048 + n];
}

// Wf [512][32000] -> bf16 hi/lo transposed [32000][512]
__global__ void p4_bsplit(const float* __restrict__ Wf) {
    __shared__ float ts[32][33];
    int v0 = blockIdx.x * 32, k0 = blockIdx.y * 32;
    int tx = threadIdx.x, ty = threadIdx.y;
#pragma unroll
    for (int i = 0; i < 4; i++)
        ts[ty + i * 8][tx] = Wf[(size_t)(k0 + ty + i * 8) * 32000 + v0 + tx];
    __syncthreads();
#pragma unroll
    for (int i = 0; i < 4; i++) {
        int r = ty + i * 8;
        float x = ts[tx][r];
        __nv_bfloat16 hi = __float2bfloat16(x);
        g_Bhi[(size_t)(v0 + r) * 512 + k0 + tx] = hi;
        g_Blo[(size_t)(v0 + r) * 512 + k0 + tx] = __float2bfloat16(x - __bfloat162float(hi));
    }
}

__global__ void p5_asplit() {
    int i = blockIdx.x * 256 + threadIdx.x;
    float x = g_attns[i];
    __nv_bfloat16 hi = __float2bfloat16(x);
    g_Ahi[i] = hi;
    g_Alo[i] = __float2bfloat16(x - __bfloat162float(hi));
}

// 128x128x8 double-buffered fp32 SGEMM (precompute only)
// MODE0: keys=memory@Wm (N=512,K=512)  MODE1: Zp=emb[tok]@Wk[:256]+b (N=2048,K=256)
template <int MODE>
__global__ __launch_bounds__(256, 2)
void sgemm_k(const float* __restrict__ A, const float* __restrict__ Bm,
             const float* __restrict__ bias, const int* __restrict__ tokens, int K) {
    const int N = (MODE == 0) ? 512 : 2048;
    __shared__ float As[2][8][128], Bs[2][8][128];
    int tid = threadIdx.x, m0 = blockIdx.y * 128, n0 = blockIdx.x * 128;
    int lm = tid >> 1, lk = (tid & 1) * 4;
    const float* Arow;
    if (MODE == 1) {
        int m = m0 + lm;
        Arow = A + (size_t)tokens[(m & 15) * 128 + (m >> 4)] * K + lk;
    } else {
        Arow = A + (size_t)(m0 + lm) * K + lk;
    }
    int bk = tid >> 5, bn = (tid & 31) * 4;
    const float* Bptr = Bm + (size_t)bk * N + n0 + bn;

    float acc[8][8];
#pragma unroll
    for (int i = 0; i < 8; i++)
#pragma unroll
        for (int j = 0; j < 8; j++) acc[i][j] = 0.f;

    {
        float4 a4 = *(const float4*)Arow;
        float4 b4 = *(const float4*)Bptr;
        As[0][lk][lm] = a4.x; As[0][lk + 1][lm] = a4.y;
        As[0][lk + 2][lm] = a4.z; As[0][lk + 3][lm] = a4.w;
        *(float4*)&Bs[0][bk][bn] = b4;
    }
    __syncthreads();

    int nst = K / 8, buf = 0, tx = tid & 15, ty = tid >> 4;
    for (int ks = 1; ks <= nst; ks++) {
        float4 na, nb;
        if (ks < nst) {
            na = *(const float4*)(Arow + ks * 8);
            nb = *(const float4*)(Bptr + (size_t)ks * 8 * N);
        }
#pragma unroll
        for (int kk = 0; kk < 8; kk++) {
            float a[8], b[8];
            *(float4*)&a[0] = *(const float4*)&As[buf][kk][ty * 4];
            *(float4*)&a[4] = *(const float4*)&As[buf][kk][64 + ty * 4];
            *(float4*)&b[0] = *(const float4*)&Bs[buf][kk][tx * 4];
            *(float4*)&b[4] = *(const float4*)&Bs[buf][kk][64 + tx * 4];
#pragma unroll
            for (int i = 0; i < 8; i++)
#pragma unroll
                for (int j = 0; j < 8; j++) acc[i][j] += a[i] * b[j];
        }
        if (ks < nst) {
            buf ^= 1;
            As[buf][lk][lm] = na.x; As[buf][lk + 1][lm] = na.y;
            As[buf][lk + 2][lm] = na.z; As[buf][lk + 3][lm] = na.w;
            *(float4*)&Bs[buf][bk][bn] = nb;
            __syncthreads();
        }
    }

#pragma unroll
    for (int i = 0; i < 8; i++) {
        int mrow = m0 + ((i < 4) ? (ty * 4 + i) : (64 + ty * 4 + i - 4));
#pragma unroll
        for (int jh = 0; jh < 2; jh++) {
            int ncol = n0 + jh * 64 + tx * 4;
            if (MODE == 0) {
                float4 v = make_float4(acc[i][jh * 4], acc[i][jh * 4 + 1],
                                       acc[i][jh * 4 + 2], acc[i][jh * 4 + 3]);
                *(float4*)(g_keys + (size_t)mrow * 512 + ncol) = v;
            } else {
#pragma unroll
                for (int jj = 0; jj < 4; jj++) {
                    int n = ncol + jj;
                    int nl2 = (n >> 9) * 4 + (n & 3);
                    g_Zp[((size_t)(mrow >> 4) * 2048 + ((n & 511) >> 2) * 16 + nl2) * 16 +
                         (mrow & 15)] = acc[i][jh * 4 + jj] + bias[n];
                }
            }
        }
    }
}

// ======================= vocab GEMM: out = attns @ Wf + bf =======================
// hi/lo bf16 split (3 products). tcgen05 path if the sm_103a feature target is
// built; portable mma.sync (HMMA) path otherwise.
__global__ __launch_bounds__(256) void vocab_gemm(const float* __restrict__ bias,
                                                  float* __restrict__ out) {
    extern __shared__ char smraw[];
    char* smb = (char*)(((uintptr_t)smraw + 1023) & ~(uintptr_t)1023);
    uint32_t sb = smem_u32(smb);
    const int tid = threadIdx.x, wid = tid >> 5, lane = tid & 31;
    const int n0 = blockIdx.x * 128, m0 = blockIdx.y * 128;

#if defined(__CUDA_ARCH_FEAT_SM103_ALL)
    // ---------------- tcgen05 path ----------------
    const uint32_t S_AH = 1024, S_AL = 17408, S_BH = 33792, S_BL = 50176;
    if (wid == 0) {
        asm volatile("tcgen05.alloc.cta_group::1.sync.aligned.shared::cta.b32 [%0], %1;"
                     :: "r"(sb), "r"(128u) : "memory");
        asm volatile("tcgen05.relinquish_alloc_permit.cta_group::1.sync.aligned;");
    }
    if (tid == 0)
        asm volatile("mbarrier.init.shared.b64 [%0], %1;" :: "r"(sb + 8), "r"(1u) : "memory");
    __syncthreads();
    uint32_t tmem;
    asm volatile("ld.shared.b32 %0, [%1];" : "=r"(tmem) : "r"(sb));

    const uint32_t idesc = (1u << 4) | (1u << 7) | (1u << 10) | (16u << 17) | (8u << 24);
    const uint64_t DBASE = (uint64_t(2) << 61) | (uint64_t(1) << 46) |
                           (uint64_t(64) << 32) | (uint64_t(1) << 16);
    uint64_t adh = DBASE | (((sb + S_AH) >> 4) & 0x3FFF);
    uint64_t adl = DBASE | (((sb + S_AL) >> 4) & 0x3FFF);
    uint64_t bdh = DBASE | (((sb + S_BH) >> 4) & 0x3FFF);
    uint64_t bdl = DBASE | (((sb + S_BL) >> 4) & 0x3FFF);

    int row = tid >> 1, half = tid & 1;
    for (int kc = 0; kc < 8; kc++) {
        const uint4* gah = (const uint4*)(g_Ahi + (size_t)(m0 + row) * 512 + kc * 64 + half * 32);
        const uint4* gal = (const uint4*)(g_Alo + (size_t)(m0 + row) * 512 + kc * 64 + half * 32);
        const uint4* gbh = (const uint4*)(g_Bhi + (size_t)(n0 + row) * 512 + kc * 64 + half * 32);
        const uint4* gbl = (const uint4*)(g_Blo + (size_t)(n0 + row) * 512 + kc * 64 + half * 32);
#pragma unroll
        for (int j = 0; j < 4; j++) {
            uint32_t so = SW128(row * 128 + half * 64 + j * 16);
            *(uint4*)(smb + S_AH + so) = gah[j];
            *(uint4*)(smb + S_AL + so) = gal[j];
            *(uint4*)(smb + S_BH + so) = gbh[j];
            *(uint4*)(smb + S_BL + so) = gbl[j];
        }
        asm volatile("fence.proxy.async.shared::cta;" ::: "memory");
        __syncthreads();
        if (tid == 0) {
#pragma unroll
            for (int ks = 0; ks < 4; ks++) {
                uint32_t en = (kc > 0) || (ks > 0);
                asm volatile(
                    "{\n\t.reg .pred p;\n\tsetp.ne.u32 p, %4, 0;\n\t"
                    "tcgen05.mma.cta_group::1.kind::f16 [%0], %1, %2, %3, {%5,%5,%5,%5}, p;\n\t"
                    "setp.ne.u32 p, 1, 0;\n\t"
                    "tcgen05.mma.cta_group::1.kind::f16 [%0], %1, %6, %3, {%5,%5,%5,%5}, p;\n\t"
                    "tcgen05.mma.cta_group::1.kind::f16 [%0], %7, %2, %3, {%5,%5,%5,%5}, p;\n\t}"
                    :: "r"(tmem), "l"(adh + ks * 2), "l"(bdh + ks * 2), "r"(idesc),
                       "r"(en), "r"(0u), "l"(bdl + ks * 2), "l"(adl + ks * 2) : "memory");
            }
            asm volatile(
                "tcgen05.commit.cta_group::1.mbarrier::arrive::one.shared::cluster.b64 [%0];"
                :: "r"(sb + 8) : "memory");
        }
        {
            uint32_t par = kc & 1;
            asm volatile(
                "{\n\t.reg .pred P;\n\t"
                "W0_%=:\n\t"
                "mbarrier.try_wait.parity.acquire.cta.shared::cta.b64 P, [%0], %1, 0x989680;\n\t"
                "@P bra W1_%=;\n\tbra W0_%=;\n\tW1_%=:\n\t}"
                :: "r"(sb + 8), "r"(par) : "memory");
        }
    }
    asm volatile("tcgen05.fence::after_thread_sync;" ::: "memory");

    if (wid < 4) {
        int m = m0 + wid * 32 + lane;
        size_t obase = ((size_t)(m & 15) * 128 + (m >> 4)) * 32000 + n0;
#pragma unroll
        for (int g = 0; g < 4; g++) {
            uint32_t r[32];
            asm volatile(
                "tcgen05.ld.sync.aligned.32x32b.x32.b32 "
                "{%0,%1,%2,%3,%4,%5,%6,%7,%8,%9,%10,%11,%12,%13,%14,%15,"
                "%16,%17,%18,%19,%20,%21,%22,%23,%24,%25,%26,%27,%28,%29,%30,%31}, [%32];"
                : "=r"(r[0]), "=r"(r[1]), "=r"(r[2]), "=r"(r[3]), "=r"(r[4]), "=r"(r[5]),
                  "=r"(r[6]), "=r"(r[7]), "=r"(r[8]), "=r"(r[9]), "=r"(r[10]), "=r"(r[11]),
                  "=r"(r[12]), "=r"(r[13]), "=r"(r[14]), "=r"(r[15]), "=r"(r[16]), "=r"(r[17]),
                  "=r"(r[18]), "=r"(r[19]), "=r"(r[20]), "=r"(r[21]), "=r"(r[22]), "=r"(r[23]),
                  "=r"(r[24]), "=r"(r[25]), "=r"(r[26]), "=r"(r[27]), "=r"(r[28]), "=r"(r[29]),
                  "=r"(r[30]), "=r"(r[31]) : "r"(tmem + g * 32));
            asm volatile("tcgen05.wait::ld.sync.aligned;" ::: "memory");
#pragma unroll
            for (int q = 0; q < 8; q++) {
                float4 bb = *(const float4*)(bias + n0 + g * 32 + q * 4);
                float4 v;
                v.x = __uint_as_float(r[q * 4 + 0]) + bb.x;
                v.y = __uint_as_float(r[q * 4 + 1]) + bb.y;
                v.z = __uint_as_float(r[q * 4 + 2]) + bb.z;
                v.w = __uint_as_float(r[q * 4 + 3]) + bb.w;
                *(float4*)(out + obase + g * 32 + q * 4) = v;
            }
        }
    }
    __syncthreads();
    if (wid == 0)
        asm volatile("tcgen05.dealloc.cta_group::1.sync.aligned.b32 %0, %1;"
                     :: "r"(tmem), "r"(128u));
#else
    // ---------------- portable mma.sync (HMMA) path ----------------
    // smem stage: 4 matrices of [128][24] bf16 (48B row stride), double buffered
    const int STG = 24576;
    const int OAH = 0, OAL = 6144, OBH = 12288, OBL = 18432;
    int mb = (wid >> 2) * 64, nb = (wid & 3) * 32;
    int row = tid >> 1, half = tid & 1;

    float acc[4][4][4];
#pragma unroll
    for (int i = 0; i < 4; i++)
#pragma unroll
        for (int j = 0; j < 4; j++)
#pragma unroll
            for (int q = 0; q < 4; q++) acc[i][j][q] = 0.f;

    const __nv_bfloat16* gah = g_Ahi + (size_t)(m0 + row) * 512 + half * 8;
    const __nv_bfloat16* gal = g_Alo + (size_t)(m0 + row) * 512 + half * 8;
    const __nv_bfloat16* gbh = g_Bhi + (size_t)(n0 + row) * 512 + half * 8;
    const __nv_bfloat16* gbl = g_Blo + (size_t)(n0 + row) * 512 + half * 8;
    uint32_t sto = row * 48 + half * 16;  // smem byte offset within a matrix

    // preload chunk 0
    {
        uint4 va = *(const uint4*)gah, vb = *(const uint4*)gal;
        uint4 vc = *(const uint4*)gbh, vd = *(const uint4*)gbl;
        *(uint4*)(smb + OAH + sto) = va;
        *(uint4*)(smb + OAL + sto) = vb;
        *(uint4*)(smb + OBH + sto) = vc;
        *(uint4*)(smb + OBL + sto) = vd;
    }
    __syncthreads();

    // per-warp ldmatrix addresses (within one matrix)
    uint32_t a_off = (uint32_t)((mb + (lane & 15)) * 48 + (lane >> 4) * 16);
    uint32_t b_off = (uint32_t)((nb + (lane & 7) + ((lane >> 4) & 1) * 8) * 48 +
                                ((lane >> 3) & 1) * 16);

    for (int kc = 0; kc < 32; kc++) {
        int buf = kc & 1;
        uint32_t sbase = sb + buf * STG;
        uint4 va, vb, vc, vd;
        if (kc < 31) {
            va = *(const uint4*)(gah + (kc + 1) * 16);
            vb = *(const uint4*)(gal + (kc + 1) * 16);
            vc = *(const uint4*)(gbh + (kc + 1) * 16);
            vd = *(const uint4*)(gbl + (kc + 1) * 16);
        }
        uint32_t aHi[4][4], aLo[4][4], bHi[4][2], bLo[4][2];
#pragma unroll
        for (int mt = 0; mt < 4; mt++) {
            LDSM4(aHi[mt][0], aHi[mt][1], aHi[mt][2], aHi[mt][3],
                  sbase + OAH + a_off + mt * 16 * 48);
            LDSM4(aLo[mt][0], aLo[mt][1], aLo[mt][2], aLo[mt][3],
                  sbase + OAL + a_off + mt * 16 * 48);
        }
#pragma unroll
        for (int p = 0; p < 2; p++) {
            uint32_t r0, r1, r2, r3;
            LDSM4(r0, r1, r2, r3, sbase + OBH + b_off + p * 16 * 48);
            bHi[p * 2][0] = r0; bHi[p * 2][1] = r1;
            bHi[p * 2 + 1][0] = r2; bHi[p * 2 + 1][1] = r3;
            LDSM4(r0, r1, r2, r3, sbase + OBL + b_off + p * 16 * 48);
            bLo[p * 2][0] = r0; bLo[p * 2][1] = r1;
            bLo[p * 2 + 1][0] = r2; bLo[p * 2 + 1][1] = r3;
        }
#pragma unroll
        for (int mt = 0; mt < 4; mt++)
#pragma unroll
            for (int nt = 0; nt < 4; nt++) {
                MMA16816(acc[mt][nt], aHi[mt], bHi[nt]);
                MMA16816(acc[mt][nt], aHi[mt], bLo[nt]);
                MMA16816(acc[mt][nt], aLo[mt], bHi[nt]);
            }
        if (kc < 31) {
            char* dst = smb + (buf ^ 1) * STG;
            *(uint4*)(dst + OAH + sto) = va;
            *(uint4*)(dst + OAL + sto) = vb;
            *(uint4*)(dst + OBH + sto) = vc;
            *(uint4*)(dst + OBL + sto) = vd;
        }
        __syncthreads();
    }

#pragma unroll
    for (int mt = 0; mt < 4; mt++)
#pragma unroll
        for (int nt = 0; nt < 4; nt++) {
            int r0 = m0 + mb + mt * 16 + (lane >> 2);
            int col = n0 + nb + nt * 8 + (lane & 3) * 2;
            float2 bb = *(const float2*)(bias + col);
            float2 v0 = make_float2(acc[mt][nt][0] + bb.x, acc[mt][nt][1] + bb.y);
            float2 v1 = make_float2(acc[mt][nt][2] + bb.x, acc[mt][nt][3] + bb.y);
            *(float2*)(out + ((size_t)(r0 & 15) * 128 + (r0 >> 4)) * 32000 + col) = v0;
            int r1 = r0 + 8;
            *(float2*)(out + ((size_t)(r1 & 15) * 128 + (r1 >> 4)) * 32000 + col) = v1;
        }
#endif
}

// K1: z = Zp[t] + u@W' ; LSTM update. CTA c -> cols c*4..c*4+3 in all 4 gates.
__global__ __launch_bounds__(256) void k1_gate(int t) {
    int c = blockIdx.x, tid = threadIdx.x;
    int rp = t & 1, wp_ = rp ^ 1;
    int nl = tid & 15, kc = tid >> 4;
    const float* wpt = g_Wp + ((size_t)c * 1024 + kc * 64) * 16 + nl;
    const float4* up = (const float4*)(g_ut[rp] + kc * 64 * 16);
    float acc[16];
#pragma unroll
    for (int i = 0; i < 16; i++) acc[i] = 0.f;
#pragma unroll 4
    for (int i = 0; i < 64; i++) {
        float w = wpt[i * 16];
        float4 u0 = up[i * 4], u1 = up[i * 4 + 1], u2 = up[i * 4 + 2], u3 = up[i * 4 + 3];
        acc[0] += w * u0.x; acc[1] += w * u0.y; acc[2] += w * u0.z; acc[3] += w * u0.w;
        acc[4] += w * u1.x; acc[5] += w * u1.y; acc[6] += w * u1.z; acc[7] += w * u1.w;
        acc[8] += w * u2.x; acc[9] += w * u2.y; acc[10] += w * u2.z; acc[11] += w * u2.w;
        acc[12] += w * u3.x; acc[13] += w * u3.y; acc[14] += w * u3.z; acc[15] += w * u3.w;
    }
    __shared__ float ps[16][16][16];
#pragma unroll
    for (int b = 0; b < 16; b++) ps[kc][nl][b] = acc[b];
    __syncthreads();
    int nlr = tid >> 4, br = tid & 15;
    float z = g_Zp[((size_t)t * 2048 + c * 16 + nlr) * 16 + br];
#pragma unroll
    for (int q = 0; q < 16; q++) z += ps[q][nlr][br];
    __shared__ float zsh[16][16];
    zsh[nlr][br] = z;
    __syncthreads();
    if (tid < 64) {
        int jl = tid & 3, b = tid >> 2, j = c * 4 + jl;
        float zi = zsh[jl][b], zf = zsh[4 + jl][b], zg = zsh[8 + jl][b], zo = zsh[12 + jl][b];
        float cc = g_c[b * 512 + j];
        float si = 1.f / (1.f + expf(-zi)), sf = 1.f / (1.f + expf(-zf));
        float so = 1.f / (1.f + expf(-zo));
        cc = sf * cc + si * tanhf(zg);
        float hh = so * tanhf(cc);
        g_c[b * 512 + j] = cc;
        g_h[b * 512 + j] = hh;
        g_ut[wp_][(512 + j) * 16 + b] = hh;
    }
}

// K2: scores + softmax + ctx, one CTA per batch.
__global__ __launch_bounds__(512) void k2_attn(const float* __restrict__ memory) {
    int b = blockIdx.x, tid = threadIdx.x;
    __shared__ float h_sh[512], w_sh[128], red[16], ctx_ps[4][512];
    h_sh[tid] = g_h[b * 512 + tid];
    __syncthreads();
    int s = tid >> 2, q = tid & 3;
    const float4* kp = (const float4*)(g_keys + ((size_t)b * 128 + s) * 512 + q * 128);
    const float* hp = h_sh + q * 128;
    float a = 0.f;
#pragma unroll 8
    for (int i = 0; i < 32; i++) {
        float4 kv = kp[i];
        a += kv.x * hp[i * 4] + kv.y * hp[i * 4 + 1] + kv.z * hp[i * 4 + 2] + kv.w * hp[i * 4 + 3];
    }
    a += __shfl_xor_sync(0xffffffffu, a, 1);
    a += __shfl_xor_sync(0xffffffffu, a, 2);
    if (q == 0) w_sh[s] = a;
    __syncthreads();
    float sc = (tid < 128) ? w_sh[tid] : -1e30f;
    float mx = sc;
#pragma unroll
    for (int o = 16; o >= 1; o >>= 1) mx = fmaxf(mx, __shfl_xor_sync(0xffffffffu, mx, o));
    if ((tid & 31) == 0) red[tid >> 5] = mx;
    __syncthreads();
    float gmx = fmaxf(fmaxf(red[0], red[1]), fmaxf(red[2], red[3]));
    __syncthreads();
    float e = (tid < 128) ? expf(sc - gmx) : 0.f;
    float sm = e;
#pragma unroll
    for (int o = 16; o >= 1; o >>= 1) sm += __shfl_xor_sync(0xffffffffu, sm, o);
    if ((tid & 31) == 0) red[tid >> 5] = sm;
    __syncthreads();
    float gsum = red[0] + red[1] + red[2] + red[3];
    if (tid < 128) w_sh[tid] = e / gsum;
    __syncthreads();
    int d4 = tid & 127, sq = tid >> 7;
    const float* mp = memory + ((size_t)b * 128 + sq * 32) * 512;
    float4 ca = make_float4(0.f, 0.f, 0.f, 0.f);
#pragma unroll 4
    for (int i = 0; i < 32; i++) {
        float w = w_sh[sq * 32 + i];
        float4 mv = *(const float4*)(mp + (size_t)i * 512 + d4 * 4);
        ca.x += w * mv.x; ca.y += w * mv.y; ca.z += w * mv.z; ca.w += w * mv.w;
    }
    *(float4*)&ctx_ps[sq][d4 * 4] = ca;
    __syncthreads();
    g_ctx[b * 512 + tid] = ctx_ps[0][tid] + ctx_ps[1][tid] + ctx_ps[2][tid] + ctx_ps[3][tid];
}

// K3: attn = [h;ctx]@Wa -> next u (attn half) + attns[t]
__global__ __launch_bounds__(256) void k3_proj(const float* __restrict__ Wa, int t) {
    int cblk = blockIdx.x, tid = threadIdx.x, wp_ = (t & 1) ^ 1;
    int b = tid & 15, kq = tid >> 4, col0 = cblk * 4;
    const float* upp = (kq < 8) ? (g_h + b * 512 + kq * 64) : (g_ctx + b * 512 + (kq - 8) * 64);
    const float* wap = Wa + (size_t)(kq * 64) * 512 + col0;
    float a0 = 0.f, a1 = 0.f, a2 = 0.f, a3 = 0.f;
#pragma unroll 4
    for (int i = 0; i < 64; i++) {
        float u = upp[i];
        float4 w4 = *(const float4*)(wap + (size_t)i * 512);
        a0 += u * w4.x; a1 += u * w4.y; a2 += u * w4.z; a3 += u * w4.w;
    }
    __shared__ float ps[16][4][16];
    ps[kq][0][b] = a0; ps[kq][1][b] = a1; ps[kq][2][b] = a2; ps[kq][3][b] = a3;
    __syncthreads();
    if (tid < 64) {
        int cl = tid >> 4, bb = tid & 15;
        float v = 0.f;
#pragma unroll
        for (int q = 0; q < 16; q++) v += ps[q][cl][bb];
        int col = col0 + cl;
        g_ut[wp_][col * 16 + bb] = v;
        g_attns[((size_t)t * 16 + bb) * 512 + col] = v;
    }
}

extern "C" void kernel_launch(void* const* d_in, const int* in_sizes, int n_in,
                              void* d_out, int out_size) {
    const int* tokens = (const int*)d_in[0];
    const float* memory = (const float*)d_in[1];
    const float* h0 = (const float*)d_in[2];
    const float* c0 = (const float*)d_in[3];
    const float* emb = (const float*)d_in[4];
    const float* Wk = (const float*)d_in[5];
    const float* Wr = (const float*)d_in[6];
    const float* bvec = (const float*)d_in[7];
    const float* Wm = (const float*)d_in[8];
    const float* Wa = (const float*)d_in[9];
    const float* Wf = (const float*)d_in[10];
    const float* bf = (const float*)d_in[11];
    float* out = (float*)d_out;

    cudaFuncSetAttribute(vocab_gemm, cudaFuncAttributeMaxDynamicSharedMemorySize, 67584);

    p0_init<<<32, 256>>>(h0, c0);
    p3_wperm<<<8192, 256>>>(Wk, Wr);
    p4_bsplit<<<dim3(1000, 16), dim3(32, 8)>>>(Wf);
    sgemm_k<0><<<dim3(4, 16), 256>>>(memory, Wm, nullptr, nullptr, 512);
    sgemm_k<1><<<dim3(16, 16), 256>>>(emb, Wk, bvec, tokens, 256);

    for (int t = 0; t < 128; t++) {
        k1_gate<<<128, 256>>>(t);
        k2_attn<<<16, 512>>>(memory);
        k3_proj<<<128, 256>>>(Wa, t);
    }

    p5_asplit<<<4096, 256>>>();
    vocab_gemm<<<dim3(250, 16), 256, 67584>>>(bf, out);
}

// round 6
// speedup vs baseline: 1.6322x; 1.5124x over previous
#include <cuda_runtime.h>
#include <cuda_bf16.h>
#include <math.h>
#include <stdint.h>

// B=16 T=128 S=128 V=32000 E=256 F=512 ; u=[attn;h] (1024), gates 4F=2048
__device__ float g_keys[2048 * 512];     // [b*128+s][e]
__device__ float g_Zp[128 * 2048 * 16];  // [t][c*16+nl][b]
__device__ float g_ut[2][1024 * 16];     // u transposed [k][b], parity buffered
__device__ float g_h[16 * 512];
__device__ float g_ctxT[512 * 16];       // ctx transposed [d][b]
__device__ float g_attns[2048 * 512];    // [t*16+b][col]
__device__ unsigned g_barc;
// bf16 split operands for tensor-core vocab GEMM
__device__ __nv_bfloat16 g_Ahi[2048 * 512];
__device__ __nv_bfloat16 g_Alo[2048 * 512];
__device__ __nv_bfloat16 g_Bhi[32000 * 512];  // Wf^T : [v][k], K contiguous
__device__ __nv_bfloat16 g_Blo[32000 * 512];

__device__ __forceinline__ uint32_t smem_u32(const void* p) {
    uint32_t a;
    asm("{ .reg .u64 t; cvta.to.shared.u64 t, %1; cvt.u32.u64 %0, t; }" : "=r"(a) : "l"(p));
    return a;
}

#define LDSM4(r0, r1, r2, r3, addr) \
    asm volatile("ldmatrix.sync.aligned.m8n8.x4.shared.b16 {%0,%1,%2,%3}, [%4];" \
                 : "=r"(r0), "=r"(r1), "=r"(r2), "=r"(r3) : "r"(addr))

#define MMA16816(d, a, b) \
    asm volatile("mma.sync.aligned.m16n8k16.row.col.f32.bf16.bf16.f32 " \
                 "{%0,%1,%2,%3}, {%4,%5,%6,%7}, {%8,%9}, {%0,%1,%2,%3};" \
                 : "+f"((d)[0]), "+f"((d)[1]), "+f"((d)[2]), "+f"((d)[3]) \
                 : "r"((a)[0]), "r"((a)[1]), "r"((a)[2]), "r"((a)[3]), \
                   "r"((b)[0]), "r"((b)[1]))

// -------- grid barrier (persistent kernel, grid=128) --------
__device__ __forceinline__ void gbar(unsigned gen) {
    __syncthreads();
    if (threadIdx.x == 0) {
        __threadfence();
        atomicAdd(&g_barc, 1u);
        unsigned tgt = gen * 128u, v;
        do {
            asm volatile("ld.acquire.gpu.u32 %0, [%1];" : "=r"(v) : "l"(&g_barc) : "memory");
        } while (v < tgt);
    }
    __syncthreads();
}

__global__ void p0_init(const float* __restrict__ h0) {
    int idx = blockIdx.x * 256 + threadIdx.x;
    if (idx == 0) g_barc = 0u;
    if (idx < 8192) {
        g_ut[0][idx] = 0.f;  // attn half (k<512) = 0
        int b = idx >> 9, j = idx & 511;
        g_ut[0][(512 + j) * 16 + b] = h0[idx];
    }
}

// Wf [512][32000] -> bf16 hi/lo transposed [32000][512]
__global__ void p4_bsplit(const float* __restrict__ Wf) {
    __shared__ float ts[32][33];
    int v0 = blockIdx.x * 32, k0 = blockIdx.y * 32;
    int tx = threadIdx.x, ty = threadIdx.y;
#pragma unroll
    for (int i = 0; i < 4; i++)
        ts[ty + i * 8][tx] = Wf[(size_t)(k0 + ty + i * 8) * 32000 + v0 + tx];
    __syncthreads();
#pragma unroll
    for (int i = 0; i < 4; i++) {
        int r = ty + i * 8;
        float x = ts[tx][r];
        __nv_bfloat16 hi = __float2bfloat16(x);
        g_Bhi[(size_t)(v0 + r) * 512 + k0 + tx] = hi;
        g_Blo[(size_t)(v0 + r) * 512 + k0 + tx] = __float2bfloat16(x - __bfloat162float(hi));
    }
}

__global__ void p5_asplit() {
    int i = blockIdx.x * 256 + threadIdx.x;
    float x = g_attns[i];
    __nv_bfloat16 hi = __float2bfloat16(x);
    g_Ahi[i] = hi;
    g_Alo[i] = __float2bfloat16(x - __bfloat162float(hi));
}

// 128x128x8 double-buffered fp32 SGEMM (precompute only)
// MODE0: keys=memory@Wm (N=512,K=512)  MODE1: Zp=emb[tok]@Wk[:256]+b (N=2048,K=256)
template <int MODE>
__global__ __launch_bounds__(256, 2)
void sgemm_k(const float* __restrict__ A, const float* __restrict__ Bm,
             const float* __restrict__ bias, const int* __restrict__ tokens, int K) {
    const int N = (MODE == 0) ? 512 : 2048;
    __shared__ float As[2][8][128], Bs[2][8][128];
    int tid = threadIdx.x, m0 = blockIdx.y * 128, n0 = blockIdx.x * 128;
    int lm = tid >> 1, lk = (tid & 1) * 4;
    const float* Arow;
    if (MODE == 1) {
        int m = m0 + lm;
        Arow = A + (size_t)tokens[(m & 15) * 128 + (m >> 4)] * K + lk;
    } else {
        Arow = A + (size_t)(m0 + lm) * K + lk;
    }
    int bk = tid >> 5, bn = (tid & 31) * 4;
    const float* Bptr = Bm + (size_t)bk * N + n0 + bn;

    float acc[8][8];
#pragma unroll
    for (int i = 0; i < 8; i++)
#pragma unroll
        for (int j = 0; j < 8; j++) acc[i][j] = 0.f;

    {
        float4 a4 = *(const float4*)Arow;
        float4 b4 = *(const float4*)Bptr;
        As[0][lk][lm] = a4.x; As[0][lk + 1][lm] = a4.y;
        As[0][lk + 2][lm] = a4.z; As[0][lk + 3][lm] = a4.w;
        *(float4*)&Bs[0][bk][bn] = b4;
    }
    __syncthreads();

    int nst = K / 8, buf = 0, tx = tid & 15, ty = tid >> 4;
    for (int ks = 1; ks <= nst; ks++) {
        float4 na, nb;
        if (ks < nst) {
            na = *(const float4*)(Arow + ks * 8);
            nb = *(const float4*)(Bptr + (size_t)ks * 8 * N);
        }
#pragma unroll
        for (int kk = 0; kk < 8; kk++) {
            float a[8], b[8];
            *(float4*)&a[0] = *(const float4*)&As[buf][kk][ty * 4];
            *(float4*)&a[4] = *(const float4*)&As[buf][kk][64 + ty * 4];
            *(float4*)&b[0] = *(const float4*)&Bs[buf][kk][tx * 4];
            *(float4*)&b[4] = *(const float4*)&Bs[buf][kk][64 + tx * 4];
#pragma unroll
            for (int i = 0; i < 8; i++)
#pragma unroll
                for (int j = 0; j < 8; j++) acc[i][j] += a[i] * b[j];
        }
        if (ks < nst) {
            buf ^= 1;
            As[buf][lk][lm] = na.x; As[buf][lk + 1][lm] = na.y;
            As[buf][lk + 2][lm] = na.z; As[buf][lk + 3][lm] = na.w;
            *(float4*)&Bs[buf][bk][bn] = nb;
            __syncthreads();
        }
    }

#pragma unroll
    for (int i = 0; i < 8; i++) {
        int mrow = m0 + ((i < 4) ? (ty * 4 + i) : (64 + ty * 4 + i - 4));
#pragma unroll
        for (int jh = 0; jh < 2; jh++) {
            int ncol = n0 + jh * 64 + tx * 4;
            if (MODE == 0) {
                float4 v = make_float4(acc[i][jh * 4], acc[i][jh * 4 + 1],
                                       acc[i][jh * 4 + 2], acc[i][jh * 4 + 3]);
                *(float4*)(g_keys + (size_t)mrow * 512 + ncol) = v;
            } else {
#pragma unroll
                for (int jj = 0; jj < 4; jj++) {
                    int n = ncol + jj;
                    int nl2 = (n >> 9) * 4 + (n & 3);
                    g_Zp[((size_t)(mrow >> 4) * 2048 + ((n & 511) >> 2) * 16 + nl2) * 16 +
                         (mrow & 15)] = acc[i][jh * 4 + jj] + bias[n];
                }
            }
        }
    }
}

// ================= fused persistent recurrence: 128 CTAs, 256 threads =================
// smem floats: sWp 16384 | sU 16384 | sWa 4096 | sPS 4096 | sZ 256  => 41216 f = 164864 B
__global__ __launch_bounds__(256) void fused_loop(const float* __restrict__ memory,
                                                  const float* __restrict__ Wk,
                                                  const float* __restrict__ Wr,
                                                  const float* __restrict__ Wa,
                                                  const float* __restrict__ c0) {
    extern __shared__ float sm[];
    float* sWp = sm;
    float* sU = sm + 16384;
    float* sWa = sm + 32768;
    float* sPS = sm + 36864;
    float* sZ = sm + 40960;
    const int c = blockIdx.x, tid = threadIdx.x;

    // prologue: gather permuted gate weights W'[k][nl] and Wa slice
    for (int it = 0; it < 64; it++) {
        int idx = tid + it * 256;
        int k = idx >> 4, nl = idx & 15;
        int n = (nl >> 2) * 512 + c * 4 + (nl & 3);
        sWp[idx] = (k < 512) ? Wk[(size_t)(256 + k) * 2048 + n]
                             : Wr[(size_t)(k - 512) * 2048 + n];
    }
    for (int it = 0; it < 16; it++) {
        int idx = tid + it * 256;
        sWa[idx] = Wa[(size_t)(idx >> 2) * 512 + c * 4 + (idx & 3)];
    }
    const int jl = tid & 3, bb = tid >> 2;  // for tid<64 LSTM lanes
    float creg = 0.f;
    if (tid < 64) creg = c0[bb * 512 + c * 4 + jl];
    __syncthreads();

    unsigned gen = 0;
    for (int t = 0; t < 128; t++) {
        int cur = t & 1, nx = cur ^ 1;
        // ---------- phase 1: u -> smem, gate GEMM, LSTM ----------
        {
            const float4* gu = (const float4*)g_ut[cur];
            float4* su4 = (float4*)sU;
#pragma unroll
            for (int i = 0; i < 16; i++) su4[tid + i * 256] = __ldcg(gu + tid + i * 256);
        }
        __syncthreads();
        {
            int nl = tid & 15, kc = tid >> 4;
            const float* wp = sWp + kc * 64 * 16 + nl;
            const float4* up = (const float4*)(sU + kc * 64 * 16);
            float acc[16];
#pragma unroll
            for (int i = 0; i < 16; i++) acc[i] = 0.f;
#pragma unroll 4
            for (int i = 0; i < 64; i++) {
                float w = wp[i * 16];
                float4 u0 = up[i * 4], u1 = up[i * 4 + 1];
                float4 u2 = up[i * 4 + 2], u3 = up[i * 4 + 3];
                acc[0] += w * u0.x; acc[1] += w * u0.y; acc[2] += w * u0.z; acc[3] += w * u0.w;
                acc[4] += w * u1.x; acc[5] += w * u1.y; acc[6] += w * u1.z; acc[7] += w * u1.w;
                acc[8] += w * u2.x; acc[9] += w * u2.y; acc[10] += w * u2.z; acc[11] += w * u2.w;
                acc[12] += w * u3.x; acc[13] += w * u3.y; acc[14] += w * u3.z; acc[15] += w * u3.w;
            }
#pragma unroll
            for (int b = 0; b < 16; b++) sPS[(kc * 16 + nl) * 16 + b] = acc[b];
        }
        __syncthreads();
        {
            int nlr = tid >> 4, br = tid & 15;
            float z = g_Zp[((size_t)t * 2048 + c * 16 + nlr) * 16 + br];
#pragma unroll
            for (int q = 0; q < 16; q++) z += sPS[(q * 16 + nlr) * 16 + br];
            sZ[nlr * 16 + br] = z;
        }
        __syncthreads();
        if (tid < 64) {
            float zi = sZ[jl * 16 + bb], zf = sZ[(4 + jl) * 16 + bb];
            float zg = sZ[(8 + jl) * 16 + bb], zo = sZ[(12 + jl) * 16 + bb];
            float si = 1.f / (1.f + expf(-zi)), sf = 1.f / (1.f + expf(-zf));
            float so = 1.f / (1.f + expf(-zo));
            creg = sf * creg + si * tanhf(zg);
            float hh = so * tanhf(creg);
            int j = c * 4 + jl;
            g_h[bb * 512 + j] = hh;
            g_ut[nx][(512 + j) * 16 + bb] = hh;
        }
        gbar(++gen);

        // ---------- phase 2: attention (CTA c < 16 handles batch c) ----------
        // EXACT r4 arithmetic: 512 work items done in 2 passes of 256 threads.
        if (c < 16) {
            float* h_sh = sPS;           // 512
            float* w_sh = sPS + 512;     // 128
            float* red = sPS + 640;      // 8
            float* ctxp = sPS + 1024;    // 4*512
            h_sh[tid] = __ldcg(g_h + c * 512 + tid);
            h_sh[tid + 256] = __ldcg(g_h + c * 512 + tid + 256);
            __syncthreads();
            // scores: item=(s,q), q-partials of 128 elems, pairwise shfl (as r4)
#pragma unroll
            for (int pass = 0; pass < 2; pass++) {
                int item = tid + pass * 256;
                int s = item >> 2, q = item & 3;
                const float4* kp =
                    (const float4*)(g_keys + ((size_t)c * 128 + s) * 512 + q * 128);
                const float* hp = h_sh + q * 128;
                float a = 0.f;
#pragma unroll 8
                for (int i = 0; i < 32; i++) {
                    float4 kv = kp[i];
                    a += kv.x * hp[i * 4] + kv.y * hp[i * 4 + 1] +
                         kv.z * hp[i * 4 + 2] + kv.w * hp[i * 4 + 3];
                }
                a += __shfl_xor_sync(0xffffffffu, a, 1);
                a += __shfl_xor_sync(0xffffffffu, a, 2);
                if (q == 0) w_sh[s] = a;
            }
            __syncthreads();
            // softmax (tids<128 carry values; identical reduction tree to r4)
            float sc = (tid < 128) ? w_sh[tid] : -1e30f;
            float mx = sc;
#pragma unroll
            for (int o = 16; o >= 1; o >>= 1)
                mx = fmaxf(mx, __shfl_xor_sync(0xffffffffu, mx, o));
            if ((tid & 31) == 0) red[tid >> 5] = mx;
            __syncthreads();
            float gmx = fmaxf(fmaxf(red[0], red[1]), fmaxf(red[2], red[3]));
            __syncthreads();
            float e = (tid < 128) ? expf(sc - gmx) : 0.f;
            float smv = e;
#pragma unroll
            for (int o = 16; o >= 1; o >>= 1) smv += __shfl_xor_sync(0xffffffffu, smv, o);
            if ((tid & 31) == 0) red[tid >> 5] = smv;
            __syncthreads();
            float gsum = red[0] + red[1] + red[2] + red[3];
            if (tid < 128) w_sh[tid] = e / gsum;
            __syncthreads();
            // ctx: item=(sq,d4), 4 sq-partials of 32 s each (as r4)
#pragma unroll
            for (int pass = 0; pass < 2; pass++) {
                int item = tid + pass * 256;
                int d4 = item & 127, sq = item >> 7;
                const float* mp = memory + ((size_t)c * 128 + sq * 32) * 512;
                float4 ca = make_float4(0.f, 0.f, 0.f, 0.f);
#pragma unroll 4
                for (int i = 0; i < 32; i++) {
                    float w = w_sh[sq * 32 + i];
                    float4 mv = *(const float4*)(mp + (size_t)i * 512 + d4 * 4);
                    ca.x += w * mv.x; ca.y += w * mv.y;
                    ca.z += w * mv.z; ca.w += w * mv.w;
                }
                *(float4*)&ctxp[sq * 512 + d4 * 4] = ca;
            }
            __syncthreads();
            for (int d = tid; d < 512; d += 256)
                g_ctxT[d * 16 + c] =
                    ctxp[d] + ctxp[512 + d] + ctxp[1024 + d] + ctxp[1536 + d];
        }
        gbar(++gen);

        // ---------- phase 3: proj attn=[h;ctx]@Wa ----------
        {
            const float4* hsrc = (const float4*)(g_ut[nx] + 512 * 16);
            const float4* csrc = (const float4*)g_ctxT;
            float4* du = (float4*)sU;
#pragma unroll
            for (int i = 0; i < 8; i++) du[tid + i * 256] = __ldcg(hsrc + tid + i * 256);
#pragma unroll
            for (int i = 0; i < 8; i++) du[2048 + tid + i * 256] = __ldcg(csrc + tid + i * 256);
        }
        __syncthreads();
        {
            int b = tid & 15, kq = tid >> 4;
            const float* uc = sU + kq * 64 * 16 + b;
            const float4* wv = (const float4*)(sWa + kq * 64 * 4);
            float a0 = 0.f, a1 = 0.f, a2 = 0.f, a3 = 0.f;
#pragma unroll 4
            for (int i = 0; i < 64; i++) {
                float u = uc[i * 16];
                float4 w4 = wv[i];
                a0 += u * w4.x; a1 += u * w4.y; a2 += u * w4.z; a3 += u * w4.w;
            }
            sPS[(kq * 4 + 0) * 16 + b] = a0;
            sPS[(kq * 4 + 1) * 16 + b] = a1;
            sPS[(kq * 4 + 2) * 16 + b] = a2;
            sPS[(kq * 4 + 3) * 16 + b] = a3;
        }
        __syncthreads();
        if (tid < 64) {
            int cl = tid >> 4, b2 = tid & 15;
            float v = 0.f;
#pragma unroll
            for (int q = 0; q < 16; q++) v += sPS[(q * 4 + cl) * 16 + b2];
            int col = c * 4 + cl;
            g_ut[nx][col * 16 + b2] = v;
            g_attns[((size_t)t * 16 + b2) * 512 + col] = v;
        }
        gbar(++gen);
    }
}

// ======================= vocab GEMM: out = attns @ Wf + bf (HMMA hi/lo split) ==========
__global__ __launch_bounds__(256) void vocab_gemm(const float* __restrict__ bias,
                                                  float* __restrict__ out) {
    extern __shared__ char smraw[];
    char* smb = (char*)(((uintptr_t)smraw + 1023) & ~(uintptr_t)1023);
    uint32_t sb = smem_u32(smb);
    const int tid = threadIdx.x, wid = tid >> 5, lane = tid & 31;
    const int n0 = blockIdx.x * 128, m0 = blockIdx.y * 128;

    const int STG = 24576;
    const int OAH = 0, OAL = 6144, OBH = 12288, OBL = 18432;
    int mb = (wid >> 2) * 64, nb = (wid & 3) * 32;
    int row = tid >> 1, half = tid & 1;

    float acc[4][4][4];
#pragma unroll
    for (int i = 0; i < 4; i++)
#pragma unroll
        for (int j = 0; j < 4; j++)
#pragma unroll
            for (int q = 0; q < 4; q++) acc[i][j][q] = 0.f;

    const __nv_bfloat16* gah = g_Ahi + (size_t)(m0 + row) * 512 + half * 8;
    const __nv_bfloat16* gal = g_Alo + (size_t)(m0 + row) * 512 + half * 8;
    const __nv_bfloat16* gbh = g_Bhi + (size_t)(n0 + row) * 512 + half * 8;
    const __nv_bfloat16* gbl = g_Blo + (size_t)(n0 + row) * 512 + half * 8;
    uint32_t sto = row * 48 + half * 16;

    {
        uint4 va = *(const uint4*)gah, vb = *(const uint4*)gal;
        uint4 vc = *(const uint4*)gbh, vd = *(const uint4*)gbl;
        *(uint4*)(smb + OAH + sto) = va;
        *(uint4*)(smb + OAL + sto) = vb;
        *(uint4*)(smb + OBH + sto) = vc;
        *(uint4*)(smb + OBL + sto) = vd;
    }
    __syncthreads();

    uint32_t a_off = (uint32_t)((mb + (lane & 15)) * 48 + (lane >> 4) * 16);
    uint32_t b_off = (uint32_t)((nb + (lane & 7) + ((lane >> 4) & 1) * 8) * 48 +
                                ((lane >> 3) & 1) * 16);

    for (int kc = 0; kc < 32; kc++) {
        int buf = kc & 1;
        uint32_t sbase = sb + buf * STG;
        uint4 va, vb, vc, vd;
        if (kc < 31) {
            va = *(const uint4*)(gah + (kc + 1) * 16);
            vb = *(const uint4*)(gal + (kc + 1) * 16);
            vc = *(const uint4*)(gbh + (kc + 1) * 16);
            vd = *(const uint4*)(gbl + (kc + 1) * 16);
        }
        uint32_t aHi[4][4], aLo[4][4], bHi[4][2], bLo[4][2];
#pragma unroll
        for (int mt = 0; mt < 4; mt++) {
            LDSM4(aHi[mt][0], aHi[mt][1], aHi[mt][2], aHi[mt][3],
                  sbase + OAH + a_off + mt * 16 * 48);
            LDSM4(aLo[mt][0], aLo[mt][1], aLo[mt][2], aLo[mt][3],
                  sbase + OAL + a_off + mt * 16 * 48);
        }
#pragma unroll
        for (int p = 0; p < 2; p++) {
            uint32_t r0, r1, r2, r3;
            LDSM4(r0, r1, r2, r3, sbase + OBH + b_off + p * 16 * 48);
            bHi[p * 2][0] = r0; bHi[p * 2][1] = r1;
            bHi[p * 2 + 1][0] = r2; bHi[p * 2 + 1][1] = r3;
            LDSM4(r0, r1, r2, r3, sbase + OBL + b_off + p * 16 * 48);
            bLo[p * 2][0] = r0; bLo[p * 2][1] = r1;
            bLo[p * 2 + 1][0] = r2; bLo[p * 2 + 1][1] = r3;
        }
#pragma unroll
        for (int mt = 0; mt < 4; mt++)
#pragma unroll
            for (int nt = 0; nt < 4; nt++) {
                MMA16816(acc[mt][nt], aHi[mt], bHi[nt]);
                MMA16816(acc[mt][nt], aHi[mt], bLo[nt]);
                MMA16816(acc[mt][nt], aLo[mt], bHi[nt]);
            }
        if (kc < 31) {
            char* dst = smb + (buf ^ 1) * STG;
            *(uint4*)(dst + OAH + sto) = va;
            *(uint4*)(dst + OAL + sto) = vb;
            *(uint4*)(dst + OBH + sto) = vc;
            *(uint4*)(dst + OBL + sto) = vd;
        }
        __syncthreads();
    }

#pragma unroll
    for (int mt = 0; mt < 4; mt++)
#pragma unroll
        for (int nt = 0; nt < 4; nt++) {
            int r0 = m0 + mb + mt * 16 + (lane >> 2);
            int col = n0 + nb + nt * 8 + (lane & 3) * 2;
            float2 bb = *(const float2*)(bias + col);
            float2 v0 = make_float2(acc[mt][nt][0] + bb.x, acc[mt][nt][1] + bb.y);
            float2 v1 = make_float2(acc[mt][nt][2] + bb.x, acc[mt][nt][3] + bb.y);
            *(float2*)(out + ((size_t)(r0 & 15) * 128 + (r0 >> 4)) * 32000 + col) = v0;
            int r1 = r0 + 8;
            *(float2*)(out + ((size_t)(r1 & 15) * 128 + (r1 >> 4)) * 32000 + col) = v1;
        }
}

extern "C" void kernel_launch(void* const* d_in, const int* in_sizes, int n_in,
                              void* d_out, int out_size) {
    const int* tokens = (const int*)d_in[0];
    const float* memory = (const float*)d_in[1];
    const float* h0 = (const float*)d_in[2];
    const float* c0 = (const float*)d_in[3];
    const float* emb = (const float*)d_in[4];
    const float* Wk = (const float*)d_in[5];
    const float* Wr = (const float*)d_in[6];
    const float* bvec = (const float*)d_in[7];
    const float* Wm = (const float*)d_in[8];
    const float* Wa = (const float*)d_in[9];
    const float* Wf = (const float*)d_in[10];
    const float* bf = (const float*)d_in[11];
    float* out = (float*)d_out;

    cudaFuncSetAttribute(vocab_gemm, cudaFuncAttributeMaxDynamicSharedMemorySize, 67584);
    cudaFuncSetAttribute(fused_loop, cudaFuncAttributeMaxDynamicSharedMemorySize, 164864);

    p0_init<<<32, 256>>>(h0);
    p4_bsplit<<<dim3(1000, 16), dim3(32, 8)>>>(Wf);
    sgemm_k<0><<<dim3(4, 16), 256>>>(memory, Wm, nullptr, nullptr, 512);
    sgemm_k<1><<<dim3(16, 16), 256>>>(emb, Wk, bvec, tokens, 256);

    fused_loop<<<128, 256, 164864>>>(memory, Wk, Wr, Wa, c0);

    p5_asplit<<<4096, 256>>>();
    vocab_gemm<<<dim3(250, 16), 256, 67584>>>(bf, out);
}

// round 7
// speedup vs baseline: 1.6464x; 1.0087x over previous
#include <cuda_runtime.h>
#include <cuda_bf16.h>
#include <math.h>
#include <stdint.h>

// B=16 T=128 S=128 V=32000 E=256 F=512 ; u=[attn;h] (1024), gates 4F=2048
__device__ float g_keys[2048 * 512];     // [b*128+s][e]
__device__ float g_Zp[128 * 2048 * 16];  // [t][c*16+nl][b]
__device__ float g_ut[2][1024 * 16];     // u transposed [k][b], parity buffered
__device__ float g_h[16 * 512];
__device__ float g_ctxT[512 * 16];       // ctx transposed [d][b]
__device__ float g_attns[2048 * 512];    // [t*16+b][col]
__device__ unsigned g_barc;
// bf16 split operands for tensor-core vocab GEMM
__device__ __nv_bfloat16 g_Ahi[2048 * 512];
__device__ __nv_bfloat16 g_Alo[2048 * 512];
__device__ __nv_bfloat16 g_Bhi[32000 * 512];  // Wf^T : [v][k], K contiguous
__device__ __nv_bfloat16 g_Blo[32000 * 512];

__device__ __forceinline__ uint32_t smem_u32(const void* p) {
    uint32_t a;
    asm("{ .reg .u64 t; cvta.to.shared.u64 t, %1; cvt.u32.u64 %0, t; }" : "=r"(a) : "l"(p));
    return a;
}

#define LDSM4(r0, r1, r2, r3, addr) \
    asm volatile("ldmatrix.sync.aligned.m8n8.x4.shared.b16 {%0,%1,%2,%3}, [%4];" \
                 : "=r"(r0), "=r"(r1), "=r"(r2), "=r"(r3) : "r"(addr))

#define MMA16816(d, a, b) \
    asm volatile("mma.sync.aligned.m16n8k16.row.col.f32.bf16.bf16.f32 " \
                 "{%0,%1,%2,%3}, {%4,%5,%6,%7}, {%8,%9}, {%0,%1,%2,%3};" \
                 : "+f"((d)[0]), "+f"((d)[1]), "+f"((d)[2]), "+f"((d)[3]) \
                 : "r"((a)[0]), "r"((a)[1]), "r"((a)[2]), "r"((a)[3]), \
                   "r"((b)[0]), "r"((b)[1]))

#define CP16(sa, gp) \
    asm volatile("cp.async.cg.shared.global [%0], [%1], 16;" :: "r"(sa), "l"(gp) : "memory")

// -------- grid barrier (persistent kernel, grid=128) --------
// Arrival: red (no-return) with release semantics -> ~0.854 cyc/arrival at LTS,
// no MEMBAR, no ATOMG serialization. Spin: acquire load.
__device__ __forceinline__ void gbar(unsigned gen) {
    __syncthreads();
    if (threadIdx.x == 0) {
        asm volatile("red.release.gpu.add.u32 [%0], 1;" :: "l"(&g_barc) : "memory");
        unsigned tgt = gen * 128u, v;
        do {
            asm volatile("ld.acquire.gpu.u32 %0, [%1];" : "=r"(v) : "l"(&g_barc) : "memory");
        } while (v < tgt);
    }
    __syncthreads();
}

__global__ void p0_init(const float* __restrict__ h0) {
    int idx = blockIdx.x * 256 + threadIdx.x;
    if (idx == 0) g_barc = 0u;
    if (idx < 8192) {
        g_ut[0][idx] = 0.f;  // attn half (k<512) = 0
        int b = idx >> 9, j = idx & 511;
        g_ut[0][(512 + j) * 16 + b] = h0[idx];
    }
}

// Wf [512][32000] -> bf16 hi/lo transposed [32000][512]
__global__ void p4_bsplit(const float* __restrict__ Wf) {
    __shared__ float ts[32][33];
    int v0 = blockIdx.x * 32, k0 = blockIdx.y * 32;
    int tx = threadIdx.x, ty = threadIdx.y;
#pragma unroll
    for (int i = 0; i < 4; i++)
        ts[ty + i * 8][tx] = Wf[(size_t)(k0 + ty + i * 8) * 32000 + v0 + tx];
    __syncthreads();
#pragma unroll
    for (int i = 0; i < 4; i++) {
        int r = ty + i * 8;
        float x = ts[tx][r];
        __nv_bfloat16 hi = __float2bfloat16(x);
        g_Bhi[(size_t)(v0 + r) * 512 + k0 + tx] = hi;
        g_Blo[(size_t)(v0 + r) * 512 + k0 + tx] = __float2bfloat16(x - __bfloat162float(hi));
    }
}

__global__ void p5_asplit() {
    int i = blockIdx.x * 256 + threadIdx.x;
    float x = g_attns[i];
    __nv_bfloat16 hi = __float2bfloat16(x);
    g_Ahi[i] = hi;
    g_Alo[i] = __float2bfloat16(x - __bfloat162float(hi));
}

// 128x128x8 double-buffered fp32 SGEMM (precompute only)
// MODE0: keys=memory@Wm (N=512,K=512)  MODE1: Zp=emb[tok]@Wk[:256]+b (N=2048,K=256)
template <int MODE>
__global__ __launch_bounds__(256, 2)
void sgemm_k(const float* __restrict__ A, const float* __restrict__ Bm,
             const float* __restrict__ bias, const int* __restrict__ tokens, int K) {
    const int N = (MODE == 0) ? 512 : 2048;
    __shared__ float As[2][8][128], Bs[2][8][128];
    int tid = threadIdx.x, m0 = blockIdx.y * 128, n0 = blockIdx.x * 128;
    int lm = tid >> 1, lk = (tid & 1) * 4;
    const float* Arow;
    if (MODE == 1) {
        int m = m0 + lm;
        Arow = A + (size_t)tokens[(m & 15) * 128 + (m >> 4)] * K + lk;
    } else {
        Arow = A + (size_t)(m0 + lm) * K + lk;
    }
    int bk = tid >> 5, bn = (tid & 31) * 4;
    const float* Bptr = Bm + (size_t)bk * N + n0 + bn;

    float acc[8][8];
#pragma unroll
    for (int i = 0; i < 8; i++)
#pragma unroll
        for (int j = 0; j < 8; j++) acc[i][j] = 0.f;

    {
        float4 a4 = *(const float4*)Arow;
        float4 b4 = *(const float4*)Bptr;
        As[0][lk][lm] = a4.x; As[0][lk + 1][lm] = a4.y;
        As[0][lk + 2][lm] = a4.z; As[0][lk + 3][lm] = a4.w;
        *(float4*)&Bs[0][bk][bn] = b4;
    }
    __syncthreads();

    int nst = K / 8, buf = 0, tx = tid & 15, ty = tid >> 4;
    for (int ks = 1; ks <= nst; ks++) {
        float4 na, nb;
        if (ks < nst) {
            na = *(const float4*)(Arow + ks * 8);
            nb = *(const float4*)(Bptr + (size_t)ks * 8 * N);
        }
#pragma unroll
        for (int kk = 0; kk < 8; kk++) {
            float a[8], b[8];
            *(float4*)&a[0] = *(const float4*)&As[buf][kk][ty * 4];
            *(float4*)&a[4] = *(const float4*)&As[buf][kk][64 + ty * 4];
            *(float4*)&b[0] = *(const float4*)&Bs[buf][kk][tx * 4];
            *(float4*)&b[4] = *(const float4*)&Bs[buf][kk][64 + tx * 4];
#pragma unroll
            for (int i = 0; i < 8; i++)
#pragma unroll
                for (int j = 0; j < 8; j++) acc[i][j] += a[i] * b[j];
        }
        if (ks < nst) {
            buf ^= 1;
            As[buf][lk][lm] = na.x; As[buf][lk + 1][lm] = na.y;
            As[buf][lk + 2][lm] = na.z; As[buf][lk + 3][lm] = na.w;
            *(float4*)&Bs[buf][bk][bn] = nb;
            __syncthreads();
        }
    }

#pragma unroll
    for (int i = 0; i < 8; i++) {
        int mrow = m0 + ((i < 4) ? (ty * 4 + i) : (64 + ty * 4 + i - 4));
#pragma unroll
        for (int jh = 0; jh < 2; jh++) {
            int ncol = n0 + jh * 64 + tx * 4;
            if (MODE == 0) {
                float4 v = make_float4(acc[i][jh * 4], acc[i][jh * 4 + 1],
                                       acc[i][jh * 4 + 2], acc[i][jh * 4 + 3]);
                *(float4*)(g_keys + (size_t)mrow * 512 + ncol) = v;
            } else {
#pragma unroll
                for (int jj = 0; jj < 4; jj++) {
                    int n = ncol + jj;
                    int nl2 = (n >> 9) * 4 + (n & 3);
                    g_Zp[((size_t)(mrow >> 4) * 2048 + ((n & 511) >> 2) * 16 + nl2) * 16 +
                         (mrow & 15)] = acc[i][jh * 4 + jj] + bias[n];
                }
            }
        }
    }
}

// ================= fused persistent recurrence: 128 CTAs, 256 threads =================
// smem floats: sWp 16384 | sU 16384 | sWa 4096 | sPS 4096 | sZ 256  => 41216 f = 164864 B
__global__ __launch_bounds__(256) void fused_loop(const float* __restrict__ memory,
                                                  const float* __restrict__ Wk,
                                                  const float* __restrict__ Wr,
                                                  const float* __restrict__ Wa,
                                                  const float* __restrict__ c0) {
    extern __shared__ float sm[];
    float* sWp = sm;
    float* sU = sm + 16384;
    float* sWa = sm + 32768;
    float* sPS = sm + 36864;
    float* sZ = sm + 40960;
    const int c = blockIdx.x, tid = threadIdx.x;

    // prologue: gather permuted gate weights W'[k][nl] and Wa slice
    for (int it = 0; it < 64; it++) {
        int idx = tid + it * 256;
        int k = idx >> 4, nl = idx & 15;
        int n = (nl >> 2) * 512 + c * 4 + (nl & 3);
        sWp[idx] = (k < 512) ? Wk[(size_t)(256 + k) * 2048 + n]
                             : Wr[(size_t)(k - 512) * 2048 + n];
    }
    for (int it = 0; it < 16; it++) {
        int idx = tid + it * 256;
        sWa[idx] = Wa[(size_t)(idx >> 2) * 512 + c * 4 + (idx & 3)];
    }
    const int jl = tid & 3, bb = tid >> 2;  // for tid<64 LSTM lanes
    float creg = 0.f;
    if (tid < 64) creg = c0[bb * 512 + c * 4 + jl];
    __syncthreads();

    unsigned gen = 0;
    for (int t = 0; t < 128; t++) {
        int cur = t & 1, nx = cur ^ 1;
        // ---------- phase 1: u -> smem, gate GEMM, LSTM ----------
        {
            const float4* gu = (const float4*)g_ut[cur];
            float4* su4 = (float4*)sU;
#pragma unroll
            for (int i = 0; i < 16; i++) su4[tid + i * 256] = __ldcg(gu + tid + i * 256);
        }
        __syncthreads();
        {
            int nl = tid & 15, kc = tid >> 4;
            const float* wp = sWp + kc * 64 * 16 + nl;
            const float4* up = (const float4*)(sU + kc * 64 * 16);
            float acc[16];
#pragma unroll
            for (int i = 0; i < 16; i++) acc[i] = 0.f;
#pragma unroll 4
            for (int i = 0; i < 64; i++) {
                float w = wp[i * 16];
                float4 u0 = up[i * 4], u1 = up[i * 4 + 1];
                float4 u2 = up[i * 4 + 2], u3 = up[i * 4 + 3];
                acc[0] += w * u0.x; acc[1] += w * u0.y; acc[2] += w * u0.z; acc[3] += w * u0.w;
                acc[4] += w * u1.x; acc[5] += w * u1.y; acc[6] += w * u1.z; acc[7] += w * u1.w;
                acc[8] += w * u2.x; acc[9] += w * u2.y; acc[10] += w * u2.z; acc[11] += w * u2.w;
                acc[12] += w * u3.x; acc[13] += w * u3.y; acc[14] += w * u3.z; acc[15] += w * u3.w;
            }
#pragma unroll
            for (int b = 0; b < 16; b++) sPS[(kc * 16 + nl) * 16 + b] = acc[b];
        }
        __syncthreads();
        {
            int nlr = tid >> 4, br = tid & 15;
            float z = g_Zp[((size_t)t * 2048 + c * 16 + nlr) * 16 + br];
#pragma unroll
            for (int q = 0; q < 16; q++) z += sPS[(q * 16 + nlr) * 16 + br];
            sZ[nlr * 16 + br] = z;
        }
        __syncthreads();
        if (tid < 64) {
            float zi = sZ[jl * 16 + bb], zf = sZ[(4 + jl) * 16 + bb];
            float zg = sZ[(8 + jl) * 16 + bb], zo = sZ[(12 + jl) * 16 + bb];
            float si = 1.f / (1.f + expf(-zi)), sf = 1.f / (1.f + expf(-zf));
            float so = 1.f / (1.f + expf(-zo));
            creg = sf * creg + si * tanhf(zg);
            float hh = so * tanhf(creg);
            int j = c * 4 + jl;
            g_h[bb * 512 + j] = hh;
            g_ut[nx][(512 + j) * 16 + bb] = hh;
        }
        gbar(++gen);

        // ---------- phase 2: attention (CTA c < 16 handles batch c) ----------
        // EXACT r4 arithmetic: 512 work items done in 2 passes of 256 threads.
        if (c < 16) {
            float* h_sh = sPS;           // 512
            float* w_sh = sPS + 512;     // 128
            float* red = sPS + 640;      // 8
            float* ctxp = sPS + 1024;    // 4*512
            h_sh[tid] = __ldcg(g_h + c * 512 + tid);
            h_sh[tid + 256] = __ldcg(g_h + c * 512 + tid + 256);
            __syncthreads();
            // scores: item=(s,q), q-partials of 128 elems, pairwise shfl (as r4)
#pragma unroll
            for (int pass = 0; pass < 2; pass++) {
                int item = tid + pass * 256;
                int s = item >> 2, q = item & 3;
                const float4* kp =
                    (const float4*)(g_keys + ((size_t)c * 128 + s) * 512 + q * 128);
                const float* hp = h_sh + q * 128;
                float a = 0.f;
#pragma unroll 8
                for (int i = 0; i < 32; i++) {
                    float4 kv = kp[i];
                    a += kv.x * hp[i * 4] + kv.y * hp[i * 4 + 1] +
                         kv.z * hp[i * 4 + 2] + kv.w * hp[i * 4 + 3];
                }
                a += __shfl_xor_sync(0xffffffffu, a, 1);
                a += __shfl_xor_sync(0xffffffffu, a, 2);
                if (q == 0) w_sh[s] = a;
            }
            __syncthreads();
            // softmax (tids<128 carry values; identical reduction tree to r4)
            float sc = (tid < 128) ? w_sh[tid] : -1e30f;
            float mx = sc;
#pragma unroll
            for (int o = 16; o >= 1; o >>= 1)
                mx = fmaxf(mx, __shfl_xor_sync(0xffffffffu, mx, o));
            if ((tid & 31) == 0) red[tid >> 5] = mx;
            __syncthreads();
            float gmx = fmaxf(fmaxf(red[0], red[1]), fmaxf(red[2], red[3]));
            __syncthreads();
            float e = (tid < 128) ? expf(sc - gmx) : 0.f;
            float smv = e;
#pragma unroll
            for (int o = 16; o >= 1; o >>= 1) smv += __shfl_xor_sync(0xffffffffu, smv, o);
            if ((tid & 31) == 0) red[tid >> 5] = smv;
            __syncthreads();
            float gsum = red[0] + red[1] + red[2] + red[3];
            if (tid < 128) w_sh[tid] = e / gsum;
            __syncthreads();
            // ctx: item=(sq,d4), 4 sq-partials of 32 s each (as r4)
#pragma unroll
            for (int pass = 0; pass < 2; pass++) {
                int item = tid + pass * 256;
                int d4 = item & 127, sq = item >> 7;
                const float* mp = memory + ((size_t)c * 128 + sq * 32) * 512;
                float4 ca = make_float4(0.f, 0.f, 0.f, 0.f);
#pragma unroll 4
                for (int i = 0; i < 32; i++) {
                    float w = w_sh[sq * 32 + i];
                    float4 mv = *(const float4*)(mp + (size_t)i * 512 + d4 * 4);
                    ca.x += w * mv.x; ca.y += w * mv.y;
                    ca.z += w * mv.z; ca.w += w * mv.w;
                }
                *(float4*)&ctxp[sq * 512 + d4 * 4] = ca;
            }
            __syncthreads();
            for (int d = tid; d < 512; d += 256)
                g_ctxT[d * 16 + c] =
                    ctxp[d] + ctxp[512 + d] + ctxp[1024 + d] + ctxp[1536 + d];
        }
        gbar(++gen);

        // ---------- phase 3: proj attn=[h;ctx]@Wa ----------
        {
            const float4* hsrc = (const float4*)(g_ut[nx] + 512 * 16);
            const float4* csrc = (const float4*)g_ctxT;
            float4* du = (float4*)sU;
#pragma unroll
            for (int i = 0; i < 8; i++) du[tid + i * 256] = __ldcg(hsrc + tid + i * 256);
#pragma unroll
            for (int i = 0; i < 8; i++) du[2048 + tid + i * 256] = __ldcg(csrc + tid + i * 256);
        }
        __syncthreads();
        {
            int b = tid & 15, kq = tid >> 4;
            const float* uc = sU + kq * 64 * 16 + b;
            const float4* wv = (const float4*)(sWa + kq * 64 * 4);
            float a0 = 0.f, a1 = 0.f, a2 = 0.f, a3 = 0.f;
#pragma unroll 4
            for (int i = 0; i < 64; i++) {
                float u = uc[i * 16];
                float4 w4 = wv[i];
                a0 += u * w4.x; a1 += u * w4.y; a2 += u * w4.z; a3 += u * w4.w;
            }
            sPS[(kq * 4 + 0) * 16 + b] = a0;
            sPS[(kq * 4 + 1) * 16 + b] = a1;
            sPS[(kq * 4 + 2) * 16 + b] = a2;
            sPS[(kq * 4 + 3) * 16 + b] = a3;
        }
        __syncthreads();
        if (tid < 64) {
            int cl = tid >> 4, b2 = tid & 15;
            float v = 0.f;
#pragma unroll
            for (int q = 0; q < 16; q++) v += sPS[(q * 4 + cl) * 16 + b2];
            int col = c * 4 + cl;
            g_ut[nx][col * 16 + b2] = v;
            g_attns[((size_t)t * 16 + b2) * 512 + col] = v;
        }
        gbar(++gen);
    }
}

// ======================= vocab GEMM: out = attns @ Wf + bf (HMMA hi/lo split) ==========
// cp.async double-buffered staging overlaps global fetch with MMA issue.
__global__ __launch_bounds__(256) void vocab_gemm(const float* __restrict__ bias,
                                                  float* __restrict__ out) {
    extern __shared__ char smraw[];
    char* smb = (char*)(((uintptr_t)smraw + 1023) & ~(uintptr_t)1023);
    uint32_t sb = smem_u32(smb);
    const int tid = threadIdx.x, wid = tid >> 5, lane = tid & 31;
    const int n0 = blockIdx.x * 128, m0 = blockIdx.y * 128;

    const int STG = 24576;
    const int OAH = 0, OAL = 6144, OBH = 12288, OBL = 18432;
    int mb = (wid >> 2) * 64, nb = (wid & 3) * 32;
    int row = tid >> 1, half = tid & 1;

    float acc[4][4][4];
#pragma unroll
    for (int i = 0; i < 4; i++)
#pragma unroll
        for (int j = 0; j < 4; j++)
#pragma unroll
            for (int q = 0; q < 4; q++) acc[i][j][q] = 0.f;

    const __nv_bfloat16* gah = g_Ahi + (size_t)(m0 + row) * 512 + half * 8;
    const __nv_bfloat16* gal = g_Alo + (size_t)(m0 + row) * 512 + half * 8;
    const __nv_bfloat16* gbh = g_Bhi + (size_t)(n0 + row) * 512 + half * 8;
    const __nv_bfloat16* gbl = g_Blo + (size_t)(n0 + row) * 512 + half * 8;
    uint32_t sto = row * 48 + half * 16;

    // prologue: stage chunk 0 into buffer 0
    CP16(sb + OAH + sto, gah);
    CP16(sb + OAL + sto, gal);
    CP16(sb + OBH + sto, gbh);
    CP16(sb + OBL + sto, gbl);
    asm volatile("cp.async.commit_group;" ::: "memory");

    uint32_t a_off = (uint32_t)((mb + (lane & 15)) * 48 + (lane >> 4) * 16);
    uint32_t b_off = (uint32_t)((nb + (lane & 7) + ((lane >> 4) & 1) * 8) * 48 +
                                ((lane >> 3) & 1) * 16);

    for (int kc = 0; kc < 32; kc++) {
        uint32_t sbase = sb + (kc & 1) * STG;
        if (kc < 31) {
            uint32_t dstb = sb + ((kc + 1) & 1) * STG;
            CP16(dstb + OAH + sto, gah + (kc + 1) * 16);
            CP16(dstb + OAL + sto, gal + (kc + 1) * 16);
            CP16(dstb + OBH + sto, gbh + (kc + 1) * 16);
            CP16(dstb + OBL + sto, gbl + (kc + 1) * 16);
            asm volatile("cp.async.commit_group;" ::: "memory");
            asm volatile("cp.async.wait_group 1;" ::: "memory");
        } else {
            asm volatile("cp.async.wait_group 0;" ::: "memory");
        }
        __syncthreads();

        uint32_t aHi[4][4], aLo[4][4], bHi[4][2], bLo[4][2];
#pragma unroll
        for (int mt = 0; mt < 4; mt++) {
            LDSM4(aHi[mt][0], aHi[mt][1], aHi[mt][2], aHi[mt][3],
                  sbase + OAH + a_off + mt * 16 * 48);
            LDSM4(aLo[mt][0], aLo[mt][1], aLo[mt][2], aLo[mt][3],
                  sbase + OAL + a_off + mt * 16 * 48);
        }
#pragma unroll
        for (int p = 0; p < 2; p++) {
            uint32_t r0, r1, r2, r3;
            LDSM4(r0, r1, r2, r3, sbase + OBH + b_off + p * 16 * 48);
            bHi[p * 2][0] = r0; bHi[p * 2][1] = r1;
            bHi[p * 2 + 1][0] = r2; bHi[p * 2 + 1][1] = r3;
            LDSM4(r0, r1, r2, r3, sbase + OBL + b_off + p * 16 * 48);
            bLo[p * 2][0] = r0; bLo[p * 2][1] = r1;
            bLo[p * 2 + 1][0] = r2; bLo[p * 2 + 1][1] = r3;
        }
#pragma unroll
        for (int mt = 0; mt < 4; mt++)
#pragma unroll
            for (int nt = 0; nt < 4; nt++) {
                MMA16816(acc[mt][nt], aHi[mt], bHi[nt]);
                MMA16816(acc[mt][nt], aHi[mt], bLo[nt]);
                MMA16816(acc[mt][nt], aLo[mt], bHi[nt]);
            }
        __syncthreads();
    }

#pragma unroll
    for (int mt = 0; mt < 4; mt++)
#pragma unroll
        for (int nt = 0; nt < 4; nt++) {
            int r0 = m0 + mb + mt * 16 + (lane >> 2);
            int col = n0 + nb + nt * 8 + (lane & 3) * 2;
            float2 bb = *(const float2*)(bias + col);
            float2 v0 = make_float2(acc[mt][nt][0] + bb.x, acc[mt][nt][1] + bb.y);
            float2 v1 = make_float2(acc[mt][nt][2] + bb.x, acc[mt][nt][3] + bb.y);
            *(float2*)(out + ((size_t)(r0 & 15) * 128 + (r0 >> 4)) * 32000 + col) = v0;
            int r1 = r0 + 8;
            *(float2*)(out + ((size_t)(r1 & 15) * 128 + (r1 >> 4)) * 32000 + col) = v1;
        }
}

extern "C" void kernel_launch(void* const* d_in, const int* in_sizes, int n_in,
                              void* d_out, int out_size) {
    const int* tokens = (const int*)d_in[0];
    const float* memory = (const float*)d_in[1];
    const float* h0 = (const float*)d_in[2];
    const float* c0 = (const float*)d_in[3];
    const float* emb = (const float*)d_in[4];
    const float* Wk = (const float*)d_in[5];
    const float* Wr = (const float*)d_in[6];
    const float* bvec = (const float*)d_in[7];
    const float* Wm = (const float*)d_in[8];
    const float* Wa = (const float*)d_in[9];
    const float* Wf = (const float*)d_in[10];
    const float* bf = (const float*)d_in[11];
    float* out = (float*)d_out;

    cudaFuncSetAttribute(vocab_gemm, cudaFuncAttributeMaxDynamicSharedMemorySize, 50176);
    cudaFuncSetAttribute(fused_loop, cudaFuncAttributeMaxDynamicSharedMemorySize, 164864);

    p0_init<<<32, 256>>>(h0);
    p4_bsplit<<<dim3(1000, 16), dim3(32, 8)>>>(Wf);
    sgemm_k<0><<<dim3(4, 16), 256>>>(memory, Wm, nullptr, nullptr, 512);
    sgemm_k<1><<<dim3(16, 16), 256>>>(emb, Wk, bvec, tokens, 256);

    fused_loop<<<128, 256, 164864>>>(memory, Wk, Wr, Wa, c0);

    p5_asplit<<<4096, 256>>>();
    vocab_gemm<<<dim3(250, 16), 256, 50176>>>(bf, out);
}

// round 8
// speedup vs baseline: 2.6511x; 1.6103x over previous
#include <cuda_runtime.h>
#include <cuda_bf16.h>
#include <math.h>
#include <stdint.h>

// B=16 T=128 S=128 V=32000 E=256 F=512 ; u=[attn;h] (1024), gates 4F=2048
__device__ float g_keys[2048 * 512];     // [b*128+s][e]
__device__ float g_Zp[128 * 2048 * 16];  // [t][c*16+nl][b]
__device__ float g_ut[2][1024 * 16];     // u transposed [k][b], parity buffered
__device__ float g_h[16 * 512];
__device__ float g_scores[16 * 128];     // [b][s]
__device__ float g_ctxT[512 * 16];       // ctx transposed [d][b]
__device__ unsigned g_barc;
// bf16 split operands for tensor-core vocab GEMM
__device__ __nv_bfloat16 g_Ahi[2048 * 512];
__device__ __nv_bfloat16 g_Alo[2048 * 512];
__device__ __nv_bfloat16 g_Bhi[32000 * 512];  // Wf^T : [v][k], K contiguous
__device__ __nv_bfloat16 g_Blo[32000 * 512];

__device__ __forceinline__ uint32_t smem_u32(const void* p) {
    uint32_t a;
    asm("{ .reg .u64 t; cvta.to.shared.u64 t, %1; cvt.u32.u64 %0, t; }" : "=r"(a) : "l"(p));
    return a;
}

#define LDSM4(r0, r1, r2, r3, addr) \
    asm volatile("ldmatrix.sync.aligned.m8n8.x4.shared.b16 {%0,%1,%2,%3}, [%4];" \
                 : "=r"(r0), "=r"(r1), "=r"(r2), "=r"(r3) : "r"(addr))

#define MMA16816(d, a, b) \
    asm volatile("mma.sync.aligned.m16n8k16.row.col.f32.bf16.bf16.f32 " \
                 "{%0,%1,%2,%3}, {%4,%5,%6,%7}, {%8,%9}, {%0,%1,%2,%3};" \
                 : "+f"((d)[0]), "+f"((d)[1]), "+f"((d)[2]), "+f"((d)[3]) \
                 : "r"((a)[0]), "r"((a)[1]), "r"((a)[2]), "r"((a)[3]), \
                   "r"((b)[0]), "r"((b)[1]))

#define CP16(sa, gp) \
    asm volatile("cp.async.cg.shared.global [%0], [%1], 16;" :: "r"(sa), "l"(gp) : "memory")

// -------- grid barrier (persistent kernel, grid=128) --------
__device__ __forceinline__ void gbar(unsigned gen) {
    __syncthreads();
    if (threadIdx.x == 0) {
        asm volatile("red.release.gpu.add.u32 [%0], 1;" :: "l"(&g_barc) : "memory");
        unsigned tgt = gen * 128u, v;
        do {
            asm volatile("ld.acquire.gpu.u32 %0, [%1];" : "=r"(v) : "l"(&g_barc) : "memory");
        } while (v < tgt);
    }
    __syncthreads();
}

__global__ void p0_init(const float* __restrict__ h0) {
    int idx = blockIdx.x * 256 + threadIdx.x;
    if (idx == 0) g_barc = 0u;
    if (idx < 8192) {
        g_ut[0][idx] = 0.f;  // attn half (k<512) = 0
        int b = idx >> 9, j = idx & 511;
        g_ut[0][(512 + j) * 16 + b] = h0[idx];
    }
}

// Wf [512][32000] -> bf16 hi/lo transposed [32000][512]
__global__ void p4_bsplit(const float* __restrict__ Wf) {
    __shared__ float ts[32][33];
    int v0 = blockIdx.x * 32, k0 = blockIdx.y * 32;
    int tx = threadIdx.x, ty = threadIdx.y;
#pragma unroll
    for (int i = 0; i < 4; i++)
        ts[ty + i * 8][tx] = Wf[(size_t)(k0 + ty + i * 8) * 32000 + v0 + tx];
    __syncthreads();
#pragma unroll
    for (int i = 0; i < 4; i++) {
        int r = ty + i * 8;
        float x = ts[tx][r];
        __nv_bfloat16 hi = __float2bfloat16(x);
        g_Bhi[(size_t)(v0 + r) * 512 + k0 + tx] = hi;
        g_Blo[(size_t)(v0 + r) * 512 + k0 + tx] = __float2bfloat16(x - __bfloat162float(hi));
    }
}

// 128x128x8 double-buffered fp32 SGEMM (precompute only)
// MODE0: keys=memory@Wm (N=512,K=512)  MODE1: Zp=emb[tok]@Wk[:256]+b (N=2048,K=256)
template <int MODE>
__global__ __launch_bounds__(256, 2)
void sgemm_k(const float* __restrict__ A, const float* __restrict__ Bm,
             const float* __restrict__ bias, const int* __restrict__ tokens, int K) {
    const int N = (MODE == 0) ? 512 : 2048;
    __shared__ float As[2][8][128], Bs[2][8][128];
    int tid = threadIdx.x, m0 = blockIdx.y * 128, n0 = blockIdx.x * 128;
    int lm = tid >> 1, lk = (tid & 1) * 4;
    const float* Arow;
    if (MODE == 1) {
        int m = m0 + lm;
        Arow = A + (size_t)tokens[(m & 15) * 128 + (m >> 4)] * K + lk;
    } else {
        Arow = A + (size_t)(m0 + lm) * K + lk;
    }
    int bk = tid >> 5, bn = (tid & 31) * 4;
    const float* Bptr = Bm + (size_t)bk * N + n0 + bn;

    float acc[8][8];
#pragma unroll
    for (int i = 0; i < 8; i++)
#pragma unroll
        for (int j = 0; j < 8; j++) acc[i][j] = 0.f;

    {
        float4 a4 = *(const float4*)Arow;
        float4 b4 = *(const float4*)Bptr;
        As[0][lk][lm] = a4.x; As[0][lk + 1][lm] = a4.y;
        As[0][lk + 2][lm] = a4.z; As[0][lk + 3][lm] = a4.w;
        *(float4*)&Bs[0][bk][bn] = b4;
    }
    __syncthreads();

    int nst = K / 8, buf = 0, tx = tid & 15, ty = tid >> 4;
    for (int ks = 1; ks <= nst; ks++) {
        float4 na, nb;
        if (ks < nst) {
            na = *(const float4*)(Arow + ks * 8);
            nb = *(const float4*)(Bptr + (size_t)ks * 8 * N);
        }
#pragma unroll
        for (int kk = 0; kk < 8; kk++) {
            float a[8], b[8];
            *(float4*)&a[0] = *(const float4*)&As[buf][kk][ty * 4];
            *(float4*)&a[4] = *(const float4*)&As[buf][kk][64 + ty * 4];
            *(float4*)&b[0] = *(const float4*)&Bs[buf][kk][tx * 4];
            *(float4*)&b[4] = *(const float4*)&Bs[buf][kk][64 + tx * 4];
#pragma unroll
            for (int i = 0; i < 8; i++)
#pragma unroll
                for (int j = 0; j < 8; j++) acc[i][j] += a[i] * b[j];
        }
        if (ks < nst) {
            buf ^= 1;
            As[buf][lk][lm] = na.x; As[buf][lk + 1][lm] = na.y;
            As[buf][lk + 2][lm] = na.z; As[buf][lk + 3][lm] = na.w;
            *(float4*)&Bs[buf][bk][bn] = nb;
            __syncthreads();
        }
    }

#pragma unroll
    for (int i = 0; i < 8; i++) {
        int mrow = m0 + ((i < 4) ? (ty * 4 + i) : (64 + ty * 4 + i - 4));
#pragma unroll
        for (int jh = 0; jh < 2; jh++) {
            int ncol = n0 + jh * 64 + tx * 4;
            if (MODE == 0) {
                float4 v = make_float4(acc[i][jh * 4], acc[i][jh * 4 + 1],
                                       acc[i][jh * 4 + 2], acc[i][jh * 4 + 3]);
                *(float4*)(g_keys + (size_t)mrow * 512 + ncol) = v;
            } else {
#pragma unroll
                for (int jj = 0; jj < 4; jj++) {
                    int n = ncol + jj;
                    int nl2 = (n >> 9) * 4 + (n & 3);
                    g_Zp[((size_t)(mrow >> 4) * 2048 + ((n & 511) >> 2) * 16 + nl2) * 16 +
                         (mrow & 15)] = acc[i][jh * 4 + jj] + bias[n];
                }
            }
        }
    }
}

// ================= fused persistent recurrence: 128 CTAs, 256 threads =================
// smem floats: sWp 16384 | sU 16384 | sWa 4096 | sPS 4096 | sZ 256 | sKeys 8192 | sMem 8192
//   => 57600 f = 230400 B
#define O_WP 0
#define O_U 16384
#define O_WA 32768
#define O_PS 36864
#define O_Z 40960
#define O_KEYS 41216
#define O_MEM 49408
__global__ __launch_bounds__(256) void fused_loop(const float* __restrict__ memory,
                                                  const float* __restrict__ Wk,
                                                  const float* __restrict__ Wr,
                                                  const float* __restrict__ Wa,
                                                  const float* __restrict__ c0) {
    extern __shared__ float sm[];
    float* sWp = sm + O_WP;
    float* sU = sm + O_U;
    float* sWa = sm + O_WA;
    float* sPS = sm + O_PS;
    float* sZ = sm + O_Z;
    float* sKeys = sm + O_KEYS;
    float* sMem = sm + O_MEM;
    const int c = blockIdx.x, tid = threadIdx.x;
    const int ab = c >> 3;             // attention batch for this CTA
    const int s0 = (c & 7) * 16;       // score s-range start
    const int d0 = (c & 7) * 64;       // ctx d-range start

    // prologue: gather permuted gate weights W'[k][nl] and Wa slice
    for (int it = 0; it < 64; it++) {
        int idx = tid + it * 256;
        int k = idx >> 4, nl = idx & 15;
        int n = (nl >> 2) * 512 + c * 4 + (nl & 3);
        sWp[idx] = (k < 512) ? Wk[(size_t)(256 + k) * 2048 + n]
                             : Wr[(size_t)(k - 512) * 2048 + n];
    }
    for (int it = 0; it < 16; it++) {
        int idx = tid + it * 256;
        sWa[idx] = Wa[(size_t)(idx >> 2) * 512 + c * 4 + (idx & 3)];
    }
    // constant smem caches: keys slice [16][512], memory slice [128][64]
    for (int i = tid; i < 8192; i += 256) {
        int r = i >> 9, k = i & 511;
        sKeys[i] = g_keys[((size_t)ab * 128 + s0 + r) * 512 + k];
    }
    for (int i = tid; i < 8192; i += 256) {
        int s = i >> 6, dl = i & 63;
        sMem[i] = memory[((size_t)ab * 128 + s) * 512 + d0 + dl];
    }
    const int jl = tid & 3, bb = tid >> 2;  // for tid<64 LSTM lanes
    float creg = 0.f;
    if (tid < 64) creg = c0[bb * 512 + c * 4 + jl];
    __syncthreads();

    unsigned gen = 0;
    for (int t = 0; t < 128; t++) {
        int cur = t & 1, nx = cur ^ 1;
        // ---------- phase 1: u -> smem, gate GEMM, LSTM ----------
        const int nlr = tid >> 4, br = tid & 15;
        float zpre = __ldcg(g_Zp + ((size_t)t * 2048 + c * 16 + nlr) * 16 + br);
        {
            const float4* gu = (const float4*)g_ut[cur];
            float4* su4 = (float4*)sU;
#pragma unroll
            for (int i = 0; i < 16; i++) su4[tid + i * 256] = __ldcg(gu + tid + i * 256);
        }
        __syncthreads();
        {
            int nl = tid & 15, kc = tid >> 4;
            const float* wp = sWp + kc * 64 * 16 + nl;
            const float4* up = (const float4*)(sU + kc * 64 * 16);
            float acc[16];
#pragma unroll
            for (int i = 0; i < 16; i++) acc[i] = 0.f;
#pragma unroll 4
            for (int i = 0; i < 64; i++) {
                float w = wp[i * 16];
                float4 u0 = up[i * 4], u1 = up[i * 4 + 1];
                float4 u2 = up[i * 4 + 2], u3 = up[i * 4 + 3];
                acc[0] += w * u0.x; acc[1] += w * u0.y; acc[2] += w * u0.z; acc[3] += w * u0.w;
                acc[4] += w * u1.x; acc[5] += w * u1.y; acc[6] += w * u1.z; acc[7] += w * u1.w;
                acc[8] += w * u2.x; acc[9] += w * u2.y; acc[10] += w * u2.z; acc[11] += w * u2.w;
                acc[12] += w * u3.x; acc[13] += w * u3.y; acc[14] += w * u3.z; acc[15] += w * u3.w;
            }
#pragma unroll
            for (int b = 0; b < 16; b++) sPS[(kc * 16 + nl) * 16 + b] = acc[b];
        }
        __syncthreads();
        {
            float z = zpre;
#pragma unroll
            for (int q = 0; q < 16; q++) z += sPS[(q * 16 + nlr) * 16 + br];
            sZ[nlr * 16 + br] = z;
        }
        __syncthreads();
        if (tid < 64) {
            float zi = sZ[jl * 16 + bb], zf = sZ[(4 + jl) * 16 + bb];
            float zg = sZ[(8 + jl) * 16 + bb], zo = sZ[(12 + jl) * 16 + bb];
            float si = 1.f / (1.f + expf(-zi)), sf = 1.f / (1.f + expf(-zf));
            float so = 1.f / (1.f + expf(-zo));
            creg = sf * creg + si * tanhf(zg);
            float hh = so * tanhf(creg);
            int j = c * 4 + jl;
            g_h[bb * 512 + j] = hh;
            g_ut[nx][(512 + j) * 16 + bb] = hh;
        }
        gbar(++gen);

        // ---------- phase 2a: scores for (ab, s0..s0+16) from smem keys ----------
        {
            float* h_sh = sPS;  // 512
            h_sh[tid] = __ldcg(g_h + ab * 512 + tid);
            h_sh[tid + 256] = __ldcg(g_h + ab * 512 + tid + 256);
            __syncthreads();
            if (tid < 64) {
                int s_l = tid >> 2, q = tid & 3;
                const float4* kp = (const float4*)(sKeys + s_l * 512 + q * 128);
                const float* hp = h_sh + q * 128;
                float a = 0.f;
#pragma unroll 8
                for (int i = 0; i < 32; i++) {
                    float4 kv = kp[i];
                    a += kv.x * hp[i * 4] + kv.y * hp[i * 4 + 1] +
                         kv.z * hp[i * 4 + 2] + kv.w * hp[i * 4 + 3];
                }
                a += __shfl_xor_sync(0xffffffffu, a, 1);
                a += __shfl_xor_sync(0xffffffffu, a, 2);
                if (q == 0) g_scores[ab * 128 + s0 + s_l] = a;
            }
        }
        gbar(++gen);

        // ---------- phase 2b: redundant softmax (exact r4 tree) + ctx d-slice ----------
        {
            float* w_sh = sPS + 512;   // 128
            float* red = sPS + 640;    // 8
            float* ctxp = sPS + 1024;  // 256
            if (tid < 128) w_sh[tid] = __ldcg(g_scores + ab * 128 + tid);
            __syncthreads();
            float sc = (tid < 128) ? w_sh[tid] : -1e30f;
            float mx = sc;
#pragma unroll
            for (int o = 16; o >= 1; o >>= 1)
                mx = fmaxf(mx, __shfl_xor_sync(0xffffffffu, mx, o));
            if ((tid & 31) == 0) red[tid >> 5] = mx;
            __syncthreads();
            float gmx = fmaxf(fmaxf(red[0], red[1]), fmaxf(red[2], red[3]));
            __syncthreads();
            float e = (tid < 128) ? expf(sc - gmx) : 0.f;
            float smv = e;
#pragma unroll
            for (int o = 16; o >= 1; o >>= 1) smv += __shfl_xor_sync(0xffffffffu, smv, o);
            if ((tid & 31) == 0) red[tid >> 5] = smv;
            __syncthreads();
            float gsum = red[0] + red[1] + red[2] + red[3];
            if (tid < 128) w_sh[tid] = e / gsum;
            __syncthreads();
            if (tid < 64) {
                int sq = tid >> 4, d4l = tid & 15;
                const float* mp = sMem + sq * 32 * 64;
                float4 ca = make_float4(0.f, 0.f, 0.f, 0.f);
#pragma unroll 4
                for (int i = 0; i < 32; i++) {
                    float w = w_sh[sq * 32 + i];
                    float4 mv = *(const float4*)(mp + i * 64 + d4l * 4);
                    ca.x += w * mv.x; ca.y += w * mv.y;
                    ca.z += w * mv.z; ca.w += w * mv.w;
                }
                *(float4*)&ctxp[sq * 64 + d4l * 4] = ca;
            }
            __syncthreads();
            if (tid < 64) {
                float v = ctxp[tid] + ctxp[64 + tid] + ctxp[128 + tid] + ctxp[192 + tid];
                g_ctxT[(d0 + tid) * 16 + ab] = v;
            }
        }
        gbar(++gen);

        // ---------- phase 3: proj attn=[h;ctx]@Wa ----------
        {
            const float4* hsrc = (const float4*)(g_ut[nx] + 512 * 16);
            const float4* csrc = (const float4*)g_ctxT;
            float4* du = (float4*)sU;
#pragma unroll
            for (int i = 0; i < 8; i++) du[tid + i * 256] = __ldcg(hsrc + tid + i * 256);
#pragma unroll
            for (int i = 0; i < 8; i++) du[2048 + tid + i * 256] = __ldcg(csrc + tid + i * 256);
        }
        __syncthreads();
        {
            int b = tid & 15, kq = tid >> 4;
            const float* uc = sU + kq * 64 * 16 + b;
            const float4* wv = (const float4*)(sWa + kq * 64 * 4);
            float a0 = 0.f, a1 = 0.f, a2 = 0.f, a3 = 0.f;
#pragma unroll 4
            for (int i = 0; i < 64; i++) {
                float u = uc[i * 16];
                float4 w4 = wv[i];
                a0 += u * w4.x; a1 += u * w4.y; a2 += u * w4.z; a3 += u * w4.w;
            }
            sPS[(kq * 4 + 0) * 16 + b] = a0;
            sPS[(kq * 4 + 1) * 16 + b] = a1;
            sPS[(kq * 4 + 2) * 16 + b] = a2;
            sPS[(kq * 4 + 3) * 16 + b] = a3;
        }
        __syncthreads();
        if (tid < 64) {
            int cl = tid >> 4, b2 = tid & 15;
            float v = 0.f;
#pragma unroll
            for (int q = 0; q < 16; q++) v += sPS[(q * 4 + cl) * 16 + b2];
            int col = c * 4 + cl;
            g_ut[nx][col * 16 + b2] = v;
            // bf16 hi/lo split written directly (replaces p5_asplit)
            __nv_bfloat16 hi = __float2bfloat16(v);
            size_t row = (size_t)t * 16 + b2;
            g_Ahi[row * 512 + col] = hi;
            g_Alo[row * 512 + col] = __float2bfloat16(v - __bfloat162float(hi));
        }
        gbar(++gen);
    }
}

// ======================= vocab GEMM: out = attns @ Wf + bf (HMMA hi/lo split) ==========
__global__ __launch_bounds__(256) void vocab_gemm(const float* __restrict__ bias,
                                                  float* __restrict__ out) {
    extern __shared__ char smraw[];
    char* smb = (char*)(((uintptr_t)smraw + 1023) & ~(uintptr_t)1023);
    uint32_t sb = smem_u32(smb);
    const int tid = threadIdx.x, wid = tid >> 5, lane = tid & 31;
    const int n0 = blockIdx.x * 128, m0 = blockIdx.y * 128;

    const int STG = 24576;
    const int OAH = 0, OAL = 6144, OBH = 12288, OBL = 18432;
    int mb = (wid >> 2) * 64, nb = (wid & 3) * 32;
    int row = tid >> 1, half = tid & 1;

    float acc[4][4][4];
#pragma unroll
    for (int i = 0; i < 4; i++)
#pragma unroll
        for (int j = 0; j < 4; j++)
#pragma unroll
            for (int q = 0; q < 4; q++) acc[i][j][q] = 0.f;

    const __nv_bfloat16* gah = g_Ahi + (size_t)(m0 + row) * 512 + half * 8;
    const __nv_bfloat16* gal = g_Alo + (size_t)(m0 + row) * 512 + half * 8;
    const __nv_bfloat16* gbh = g_Bhi + (size_t)(n0 + row) * 512 + half * 8;
    const __nv_bfloat16* gbl = g_Blo + (size_t)(n0 + row) * 512 + half * 8;
    uint32_t sto = row * 48 + half * 16;

    CP16(sb + OAH + sto, gah);
    CP16(sb + OAL + sto, gal);
    CP16(sb + OBH + sto, gbh);
    CP16(sb + OBL + sto, gbl);
    asm volatile("cp.async.commit_group;" ::: "memory");

    uint32_t a_off = (uint32_t)((mb + (lane & 15)) * 48 + (lane >> 4) * 16);
    uint32_t b_off = (uint32_t)((nb + (lane & 7) + ((lane >> 4) & 1) * 8) * 48 +
                                ((lane >> 3) & 1) * 16);

    for (int kc = 0; kc < 32; kc++) {
        uint32_t sbase = sb + (kc & 1) * STG;
        if (kc < 31) {
            uint32_t dstb = sb + ((kc + 1) & 1) * STG;
            CP16(dstb + OAH + sto, gah + (kc + 1) * 16);
            CP16(dstb + OAL + sto, gal + (kc + 1) * 16);
            CP16(dstb + OBH + sto, gbh + (kc + 1) * 16);
            CP16(dstb + OBL + sto, gbl + (kc + 1) * 16);
            asm volatile("cp.async.commit_group;" ::: "memory");
            asm volatile("cp.async.wait_group 1;" ::: "memory");
        } else {
            asm volatile("cp.async.wait_group 0;" ::: "memory");
        }
        __syncthreads();

        uint32_t aHi[4][4], aLo[4][4], bHi[4][2], bLo[4][2];
#pragma unroll
        for (int mt = 0; mt < 4; mt++) {
            LDSM4(aHi[mt][0], aHi[mt][1], aHi[mt][2], aHi[mt][3],
                  sbase + OAH + a_off + mt * 16 * 48);
            LDSM4(aLo[mt][0], aLo[mt][1], aLo[mt][2], aLo[mt][3],
                  sbase + OAL + a_off + mt * 16 * 48);
        }
#pragma unroll
        for (int p = 0; p < 2; p++) {
            uint32_t r0, r1, r2, r3;
            LDSM4(r0, r1, r2, r3, sbase + OBH + b_off + p * 16 * 48);
            bHi[p * 2][0] = r0; bHi[p * 2][1] = r1;
            bHi[p * 2 + 1][0] = r2; bHi[p * 2 + 1][1] = r3;
            LDSM4(r0, r1, r2, r3, sbase + OBL + b_off + p * 16 * 48);
            bLo[p * 2][0] = r0; bLo[p * 2][1] = r1;
            bLo[p * 2 + 1][0] = r2; bLo[p * 2 + 1][1] = r3;
        }
#pragma unroll
        for (int mt = 0; mt < 4; mt++)
#pragma unroll
            for (int nt = 0; nt < 4; nt++) {
                MMA16816(acc[mt][nt], aHi[mt], bHi[nt]);
                MMA16816(acc[mt][nt], aHi[mt], bLo[nt]);
                MMA16816(acc[mt][nt], aLo[mt], bHi[nt]);
            }
        __syncthreads();
    }

#pragma unroll
    for (int mt = 0; mt < 4; mt++)
#pragma unroll
        for (int nt = 0; nt < 4; nt++) {
            int r0 = m0 + mb + mt * 16 + (lane >> 2);
            int col = n0 + nb + nt * 8 + (lane & 3) * 2;
            float2 bb = *(const float2*)(bias + col);
            float2 v0 = make_float2(acc[mt][nt][0] + bb.x, acc[mt][nt][1] + bb.y);
            float2 v1 = make_float2(acc[mt][nt][2] + bb.x, acc[mt][nt][3] + bb.y);
            *(float2*)(out + ((size_t)(r0 & 15) * 128 + (r0 >> 4)) * 32000 + col) = v0;
            int r1 = r0 + 8;
            *(float2*)(out + ((size_t)(r1 & 15) * 128 + (r1 >> 4)) * 32000 + col) = v1;
        }
}

extern "C" void kernel_launch(void* const* d_in, const int* in_sizes, int n_in,
                              void* d_out, int out_size) {
    const int* tokens = (const int*)d_in[0];
    const float* memory = (const float*)d_in[1];
    const float* h0 = (const float*)d_in[2];
    const float* c0 = (const float*)d_in[3];
    const float* emb = (const float*)d_in[4];
    const float* Wk = (const float*)d_in[5];
    const float* Wr = (const float*)d_in[6];
    const float* bvec = (const float*)d_in[7];
    const float* Wm = (const float*)d_in[8];
    const float* Wa = (const float*)d_in[9];
    const float* Wf = (const float*)d_in[10];
    const float* bf = (const float*)d_in[11];
    float* out = (float*)d_out;

    cudaFuncSetAttribute(vocab_gemm, cudaFuncAttributeMaxDynamicSharedMemorySize, 50176);
    cudaFuncSetAttribute(fused_loop, cudaFuncAttributeMaxDynamicSharedMemorySize, 230400);

    p0_init<<<32, 256>>>(h0);
    p4_bsplit<<<dim3(1000, 16), dim3(32, 8)>>>(Wf);
    sgemm_k<0><<<dim3(4, 16), 256>>>(memory, Wm, nullptr, nullptr, 512);
    sgemm_k<1><<<dim3(16, 16), 256>>>(emb, Wk, bvec, tokens, 256);

    fused_loop<<<128, 256, 230400>>>(memory, Wk, Wr, Wa, c0);

    vocab_gemm<<<dim3(250, 16), 256, 50176>>>(bf, out);
}

// round 9
// speedup vs baseline: 2.8155x; 1.0620x over previous
#include <cuda_runtime.h>
#include <cuda_bf16.h>
#include <math.h>
#include <stdint.h>

// B=16 T=128 S=128 V=32000 E=256 F=512 ; u=[attn;h] (1024), gates 4F=2048
__device__ float g_keys[2048 * 512];     // [b*128+s][e]
__device__ float g_Zp[128 * 2048 * 16];  // [t][c*16+nl][b]
__device__ float g_ut[2][1024 * 16];     // u transposed [k][b], parity buffered
__device__ float g_h[16 * 512];
__device__ float g_scores[16 * 128];     // [b][s]
__device__ float g_ctxT[512 * 16];       // ctx transposed [d][b]
__device__ unsigned g_barc;
// bf16 split operands for tensor-core vocab GEMM
__device__ __nv_bfloat16 g_Ahi[2048 * 512];
__device__ __nv_bfloat16 g_Alo[2048 * 512];
__device__ __nv_bfloat16 g_Bhi[32000 * 512];  // Wf^T : [v][k], K contiguous
__device__ __nv_bfloat16 g_Blo[32000 * 512];

__device__ __forceinline__ uint32_t smem_u32(const void* p) {
    uint32_t a;
    asm("{ .reg .u64 t; cvta.to.shared.u64 t, %1; cvt.u32.u64 %0, t; }" : "=r"(a) : "l"(p));
    return a;
}

#define LDSM4(r0, r1, r2, r3, addr) \
    asm volatile("ldmatrix.sync.aligned.m8n8.x4.shared.b16 {%0,%1,%2,%3}, [%4];" \
                 : "=r"(r0), "=r"(r1), "=r"(r2), "=r"(r3) : "r"(addr))

#define MMA16816(d, a0, a1, a2, a3, b0, b1) \
    asm volatile("mma.sync.aligned.m16n8k16.row.col.f32.bf16.bf16.f32 " \
                 "{%0,%1,%2,%3}, {%4,%5,%6,%7}, {%8,%9}, {%0,%1,%2,%3};" \
                 : "+f"((d)[0]), "+f"((d)[1]), "+f"((d)[2]), "+f"((d)[3]) \
                 : "r"(a0), "r"(a1), "r"(a2), "r"(a3), "r"(b0), "r"(b1))

#define CP16(sa, gp) \
    asm volatile("cp.async.cg.shared.global [%0], [%1], 16;" :: "r"(sa), "l"(gp) : "memory")

// -------- grid barrier (persistent kernel, grid=128) --------
__device__ __forceinline__ void gbar(unsigned gen) {
    __syncthreads();
    if (threadIdx.x == 0) {
        asm volatile("red.release.gpu.add.u32 [%0], 1;" :: "l"(&g_barc) : "memory");
        unsigned tgt = gen * 128u, v;
        do {
            asm volatile("ld.acquire.gpu.u32 %0, [%1];" : "=r"(v) : "l"(&g_barc) : "memory");
        } while (v < tgt);
    }
    __syncthreads();
}

__global__ void p0_init(const float* __restrict__ h0) {
    int idx = blockIdx.x * 256 + threadIdx.x;
    if (idx == 0) g_barc = 0u;
    if (idx < 8192) {
        g_ut[0][idx] = 0.f;  // attn half (k<512) = 0
        int b = idx >> 9, j = idx & 511;
        g_ut[0][(512 + j) * 16 + b] = h0[idx];
    }
}

// Wf [512][32000] -> bf16 hi/lo transposed [32000][512]
__global__ void p4_bsplit(const float* __restrict__ Wf) {
    __shared__ float ts[32][33];
    int v0 = blockIdx.x * 32, k0 = blockIdx.y * 32;
    int tx = threadIdx.x, ty = threadIdx.y;
#pragma unroll
    for (int i = 0; i < 4; i++)
        ts[ty + i * 8][tx] = Wf[(size_t)(k0 + ty + i * 8) * 32000 + v0 + tx];
    __syncthreads();
#pragma unroll
    for (int i = 0; i < 4; i++) {
        int r = ty + i * 8;
        float x = ts[tx][r];
        __nv_bfloat16 hi = __float2bfloat16(x);
        g_Bhi[(size_t)(v0 + r) * 512 + k0 + tx] = hi;
        g_Blo[(size_t)(v0 + r) * 512 + k0 + tx] = __float2bfloat16(x - __bfloat162float(hi));
    }
}

// 128x128x8 double-buffered fp32 SGEMM (precompute only)
// MODE0: keys=memory@Wm (N=512,K=512)  MODE1: Zp=emb[tok]@Wk[:256]+b (N=2048,K=256)
template <int MODE>
__global__ __launch_bounds__(256, 2)
void sgemm_k(const float* __restrict__ A, const float* __restrict__ Bm,
             const float* __restrict__ bias, const int* __restrict__ tokens, int K) {
    const int N = (MODE == 0) ? 512 : 2048;
    __shared__ float As[2][8][128], Bs[2][8][128];
    int tid = threadIdx.x, m0 = blockIdx.y * 128, n0 = blockIdx.x * 128;
    int lm = tid >> 1, lk = (tid & 1) * 4;
    const float* Arow;
    if (MODE == 1) {
        int m = m0 + lm;
        Arow = A + (size_t)tokens[(m & 15) * 128 + (m >> 4)] * K + lk;
    } else {
        Arow = A + (size_t)(m0 + lm) * K + lk;
    }
    int bk = tid >> 5, bn = (tid & 31) * 4;
    const float* Bptr = Bm + (size_t)bk * N + n0 + bn;

    float acc[8][8];
#pragma unroll
    for (int i = 0; i < 8; i++)
#pragma unroll
        for (int j = 0; j < 8; j++) acc[i][j] = 0.f;

    {
        float4 a4 = *(const float4*)Arow;
        float4 b4 = *(const float4*)Bptr;
        As[0][lk][lm] = a4.x; As[0][lk + 1][lm] = a4.y;
        As[0][lk + 2][lm] = a4.z; As[0][lk + 3][lm] = a4.w;
        *(float4*)&Bs[0][bk][bn] = b4;
    }
    __syncthreads();

    int nst = K / 8, buf = 0, tx = tid & 15, ty = tid >> 4;
    for (int ks = 1; ks <= nst; ks++) {
        float4 na, nb;
        if (ks < nst) {
            na = *(const float4*)(Arow + ks * 8);
            nb = *(const float4*)(Bptr + (size_t)ks * 8 * N);
        }
#pragma unroll
        for (int kk = 0; kk < 8; kk++) {
            float a[8], b[8];
            *(float4*)&a[0] = *(const float4*)&As[buf][kk][ty * 4];
            *(float4*)&a[4] = *(const float4*)&As[buf][kk][64 + ty * 4];
            *(float4*)&b[0] = *(const float4*)&Bs[buf][kk][tx * 4];
            *(float4*)&b[4] = *(const float4*)&Bs[buf][kk][64 + tx * 4];
#pragma unroll
            for (int i = 0; i < 8; i++)
#pragma unroll
                for (int j = 0; j < 8; j++) acc[i][j] += a[i] * b[j];
        }
        if (ks < nst) {
            buf ^= 1;
            As[buf][lk][lm] = na.x; As[buf][lk + 1][lm] = na.y;
            As[buf][lk + 2][lm] = na.z; As[buf][lk + 3][lm] = na.w;
            *(float4*)&Bs[buf][bk][bn] = nb;
            __syncthreads();
        }
    }

#pragma unroll
    for (int i = 0; i < 8; i++) {
        int mrow = m0 + ((i < 4) ? (ty * 4 + i) : (64 + ty * 4 + i - 4));
#pragma unroll
        for (int jh = 0; jh < 2; jh++) {
            int ncol = n0 + jh * 64 + tx * 4;
            if (MODE == 0) {
                float4 v = make_float4(acc[i][jh * 4], acc[i][jh * 4 + 1],
                                       acc[i][jh * 4 + 2], acc[i][jh * 4 + 3]);
                *(float4*)(g_keys + (size_t)mrow * 512 + ncol) = v;
            } else {
#pragma unroll
                for (int jj = 0; jj < 4; jj++) {
                    int n = ncol + jj;
                    int nl2 = (n >> 9) * 4 + (n & 3);
                    g_Zp[((size_t)(mrow >> 4) * 2048 + ((n & 511) >> 2) * 16 + nl2) * 16 +
                         (mrow & 15)] = acc[i][jh * 4 + jj] + bias[n];
                }
            }
        }
    }
}

// ================= fused persistent recurrence: 128 CTAs, 256 threads =================
// smem floats: sWp 16384 | sU 16384 | sWa 4096 | sPS 4096 | sZ 256 | sKeys 8192 | sMem 8192
//   => 57600 f = 230400 B
#define O_WP 0
#define O_U 16384
#define O_WA 32768
#define O_PS 36864
#define O_Z 40960
#define O_KEYS 41216
#define O_MEM 49408
__global__ __launch_bounds__(256) void fused_loop(const float* __restrict__ memory,
                                                  const float* __restrict__ Wk,
                                                  const float* __restrict__ Wr,
                                                  const float* __restrict__ Wa,
                                                  const float* __restrict__ c0) {
    extern __shared__ float sm[];
    float* sWp = sm + O_WP;
    float* sU = sm + O_U;
    float* sWa = sm + O_WA;
    float* sPS = sm + O_PS;
    float* sZ = sm + O_Z;
    float* sKeys = sm + O_KEYS;
    float* sMem = sm + O_MEM;
    const int c = blockIdx.x, tid = threadIdx.x;
    const int ab = c >> 3;             // attention batch for this CTA
    const int s0 = (c & 7) * 16;       // score s-range start
    const int d0 = (c & 7) * 64;       // ctx d-range start

    // prologue: gather permuted gate weights W'[k][nl] and Wa slice
    for (int it = 0; it < 64; it++) {
        int idx = tid + it * 256;
        int k = idx >> 4, nl = idx & 15;
        int n = (nl >> 2) * 512 + c * 4 + (nl & 3);
        sWp[idx] = (k < 512) ? Wk[(size_t)(256 + k) * 2048 + n]
                             : Wr[(size_t)(k - 512) * 2048 + n];
    }
    for (int it = 0; it < 16; it++) {
        int idx = tid + it * 256;
        sWa[idx] = Wa[(size_t)(idx >> 2) * 512 + c * 4 + (idx & 3)];
    }
    // constant smem caches: keys slice [16][512], memory slice [128][64]
    for (int i = tid; i < 8192; i += 256) {
        int r = i >> 9, k = i & 511;
        sKeys[i] = g_keys[((size_t)ab * 128 + s0 + r) * 512 + k];
    }
    for (int i = tid; i < 8192; i += 256) {
        int s = i >> 6, dl = i & 63;
        sMem[i] = memory[((size_t)ab * 128 + s) * 512 + d0 + dl];
    }
    const int jl = tid & 3, bb = tid >> 2;  // for tid<64 LSTM lanes
    float creg = 0.f;
    if (tid < 64) creg = c0[bb * 512 + c * 4 + jl];
    __syncthreads();

    unsigned gen = 0;
    for (int t = 0; t < 128; t++) {
        int cur = t & 1, nx = cur ^ 1;
        // ---------- phase 1: u -> smem, gate GEMM, LSTM ----------
        const int nlr = tid >> 4, br = tid & 15;
        float zpre = __ldcg(g_Zp + ((size_t)t * 2048 + c * 16 + nlr) * 16 + br);
        {
            const float4* gu = (const float4*)g_ut[cur];
            float4* su4 = (float4*)sU;
#pragma unroll
            for (int i = 0; i < 16; i++) su4[tid + i * 256] = __ldcg(gu + tid + i * 256);
        }
        __syncthreads();
        {
            int nl = tid & 15, kc = tid >> 4;
            const float* wp = sWp + kc * 64 * 16 + nl;
            const float4* up = (const float4*)(sU + kc * 64 * 16);
            float acc[16];
#pragma unroll
            for (int i = 0; i < 16; i++) acc[i] = 0.f;
#pragma unroll 4
            for (int i = 0; i < 64; i++) {
                float w = wp[i * 16];
                float4 u0 = up[i * 4], u1 = up[i * 4 + 1];
                float4 u2 = up[i * 4 + 2], u3 = up[i * 4 + 3];
                acc[0] += w * u0.x; acc[1] += w * u0.y; acc[2] += w * u0.z; acc[3] += w * u0.w;
                acc[4] += w * u1.x; acc[5] += w * u1.y; acc[6] += w * u1.z; acc[7] += w * u1.w;
                acc[8] += w * u2.x; acc[9] += w * u2.y; acc[10] += w * u2.z; acc[11] += w * u2.w;
                acc[12] += w * u3.x; acc[13] += w * u3.y; acc[14] += w * u3.z; acc[15] += w * u3.w;
            }
#pragma unroll
            for (int b = 0; b < 16; b++) sPS[(kc * 16 + nl) * 16 + b] = acc[b];
        }
        __syncthreads();
        {
            float z = zpre;
#pragma unroll
            for (int q = 0; q < 16; q++) z += sPS[(q * 16 + nlr) * 16 + br];
            sZ[nlr * 16 + br] = z;
        }
        __syncthreads();
        if (tid < 64) {
            float zi = sZ[jl * 16 + bb], zf = sZ[(4 + jl) * 16 + bb];
            float zg = sZ[(8 + jl) * 16 + bb], zo = sZ[(12 + jl) * 16 + bb];
            float si = 1.f / (1.f + expf(-zi)), sf = 1.f / (1.f + expf(-zf));
            float so = 1.f / (1.f + expf(-zo));
            creg = sf * creg + si * tanhf(zg);
            float hh = so * tanhf(creg);
            int j = c * 4 + jl;
            g_h[bb * 512 + j] = hh;
            g_ut[nx][(512 + j) * 16 + bb] = hh;
        }
        gbar(++gen);

        // ---------- phase 2a: scores for (ab, s0..s0+16) from smem keys ----------
        {
            float* h_sh = sPS;  // 512
            h_sh[tid] = __ldcg(g_h + ab * 512 + tid);
            h_sh[tid + 256] = __ldcg(g_h + ab * 512 + tid + 256);
            __syncthreads();
            if (tid < 64) {
                int s_l = tid >> 2, q = tid & 3;
                const float4* kp = (const float4*)(sKeys + s_l * 512 + q * 128);
                const float* hp = h_sh + q * 128;
                float a = 0.f;
#pragma unroll 8
                for (int i = 0; i < 32; i++) {
                    float4 kv = kp[i];
                    a += kv.x * hp[i * 4] + kv.y * hp[i * 4 + 1] +
                         kv.z * hp[i * 4 + 2] + kv.w * hp[i * 4 + 3];
                }
                a += __shfl_xor_sync(0xffffffffu, a, 1);
                a += __shfl_xor_sync(0xffffffffu, a, 2);
                if (q == 0) g_scores[ab * 128 + s0 + s_l] = a;
            }
        }
        gbar(++gen);

        // ---------- phase 2b: redundant softmax (exact r4 tree) + ctx d-slice ----------
        {
            float* w_sh = sPS + 512;   // 128
            float* red = sPS + 640;    // 8
            float* ctxp = sPS + 1024;  // 256
            if (tid < 128) w_sh[tid] = __ldcg(g_scores + ab * 128 + tid);
            __syncthreads();
            float sc = (tid < 128) ? w_sh[tid] : -1e30f;
            float mx = sc;
#pragma unroll
            for (int o = 16; o >= 1; o >>= 1)
                mx = fmaxf(mx, __shfl_xor_sync(0xffffffffu, mx, o));
            if ((tid & 31) == 0) red[tid >> 5] = mx;
            __syncthreads();
            float gmx = fmaxf(fmaxf(red[0], red[1]), fmaxf(red[2], red[3]));
            __syncthreads();
            float e = (tid < 128) ? expf(sc - gmx) : 0.f;
            float smv = e;
#pragma unroll
            for (int o = 16; o >= 1; o >>= 1) smv += __shfl_xor_sync(0xffffffffu, smv, o);
            if ((tid & 31) == 0) red[tid >> 5] = smv;
            __syncthreads();
            float gsum = red[0] + red[1] + red[2] + red[3];
            if (tid < 128) w_sh[tid] = e / gsum;
            __syncthreads();
            if (tid < 64) {
                int sq = tid >> 4, d4l = tid & 15;
                const float* mp = sMem + sq * 32 * 64;
                float4 ca = make_float4(0.f, 0.f, 0.f, 0.f);
#pragma unroll 4
                for (int i = 0; i < 32; i++) {
                    float w = w_sh[sq * 32 + i];
                    float4 mv = *(const float4*)(mp + i * 64 + d4l * 4);
                    ca.x += w * mv.x; ca.y += w * mv.y;
                    ca.z += w * mv.z; ca.w += w * mv.w;
                }
                *(float4*)&ctxp[sq * 64 + d4l * 4] = ca;
            }
            __syncthreads();
            if (tid < 64) {
                float v = ctxp[tid] + ctxp[64 + tid] + ctxp[128 + tid] + ctxp[192 + tid];
                g_ctxT[(d0 + tid) * 16 + ab] = v;
            }
        }
        gbar(++gen);

        // ---------- phase 3: proj attn=[h;ctx]@Wa ----------
        {
            const float4* hsrc = (const float4*)(g_ut[nx] + 512 * 16);
            const float4* csrc = (const float4*)g_ctxT;
            float4* du = (float4*)sU;
#pragma unroll
            for (int i = 0; i < 8; i++) du[tid + i * 256] = __ldcg(hsrc + tid + i * 256);
#pragma unroll
            for (int i = 0; i < 8; i++) du[2048 + tid + i * 256] = __ldcg(csrc + tid + i * 256);
        }
        __syncthreads();
        {
            int b = tid & 15, kq = tid >> 4;
            const float* uc = sU + kq * 64 * 16 + b;
            const float4* wv = (const float4*)(sWa + kq * 64 * 4);
            float a0 = 0.f, a1 = 0.f, a2 = 0.f, a3 = 0.f;
#pragma unroll 4
            for (int i = 0; i < 64; i++) {
                float u = uc[i * 16];
                float4 w4 = wv[i];
                a0 += u * w4.x; a1 += u * w4.y; a2 += u * w4.z; a3 += u * w4.w;
            }
            sPS[(kq * 4 + 0) * 16 + b] = a0;
            sPS[(kq * 4 + 1) * 16 + b] = a1;
            sPS[(kq * 4 + 2) * 16 + b] = a2;
            sPS[(kq * 4 + 3) * 16 + b] = a3;
        }
        __syncthreads();
        if (tid < 64) {
            int cl = tid >> 4, b2 = tid & 15;
            float v = 0.f;
#pragma unroll
            for (int q = 0; q < 16; q++) v += sPS[(q * 4 + cl) * 16 + b2];
            int col = c * 4 + cl;
            g_ut[nx][col * 16 + b2] = v;
            // bf16 hi/lo split written directly (replaces p5_asplit)
            __nv_bfloat16 hi = __float2bfloat16(v);
            size_t row = (size_t)t * 16 + b2;
            g_Ahi[row * 512 + col] = hi;
            g_Alo[row * 512 + col] = __float2bfloat16(v - __bfloat162float(hi));
        }
        gbar(++gen);
    }
}

// ======================= vocab GEMM: out = attns @ Wf + bf (HMMA hi/lo split) ==========
// 3-stage cp.async pipeline, ONE __syncthreads/iter, 2 CTAs/SM.
__global__ __launch_bounds__(256, 2) void vocab_gemm(const float* __restrict__ bias,
                                                     float* __restrict__ out) {
    extern __shared__ char smraw[];
    char* smb = (char*)(((uintptr_t)smraw + 1023) & ~(uintptr_t)1023);
    uint32_t sb = smem_u32(smb);
    const int tid = threadIdx.x, wid = tid >> 5, lane = tid & 31;
    const int n0 = blockIdx.x * 128, m0 = blockIdx.y * 128;

    const int STG = 24576;
    const int OAH = 0, OAL = 6144, OBH = 12288, OBL = 18432;
    int mb = (wid >> 2) * 64, nb = (wid & 3) * 32;
    int row = tid >> 1, half = tid & 1;

    float acc[4][4][4];
#pragma unroll
    for (int i = 0; i < 4; i++)
#pragma unroll
        for (int j = 0; j < 4; j++)
#pragma unroll
            for (int q = 0; q < 4; q++) acc[i][j][q] = 0.f;

    const __nv_bfloat16* gah = g_Ahi + (size_t)(m0 + row) * 512 + half * 8;
    const __nv_bfloat16* gal = g_Alo + (size_t)(m0 + row) * 512 + half * 8;
    const __nv_bfloat16* gbh = g_Bhi + (size_t)(n0 + row) * 512 + half * 8;
    const __nv_bfloat16* gbl = g_Blo + (size_t)(n0 + row) * 512 + half * 8;
    uint32_t sto = row * 48 + half * 16;

    // prologue: stage chunks 0 and 1 into stages 0 and 1 (one commit group each)
#pragma unroll
    for (int pc = 0; pc < 2; pc++) {
        uint32_t dstb = sb + pc * STG;
        CP16(dstb + OAH + sto, gah + pc * 16);
        CP16(dstb + OAL + sto, gal + pc * 16);
        CP16(dstb + OBH + sto, gbh + pc * 16);
        CP16(dstb + OBL + sto, gbl + pc * 16);
        asm volatile("cp.async.commit_group;" ::: "memory");
    }

    uint32_t a_off = (uint32_t)((mb + (lane & 15)) * 48 + (lane >> 4) * 16);
    uint32_t b_off = (uint32_t)((nb + (lane & 7) + ((lane >> 4) & 1) * 8) * 48 +
                                ((lane >> 3) & 1) * 16);

    int stage = 0;
    for (int kc = 0; kc < 32; kc++) {
        // chunk kc arrived when all but the newest group are done
        asm volatile("cp.async.wait_group 1;" ::: "memory");
        __syncthreads();
        // issue chunk kc+2 into the stage drained last iteration (safe post-sync)
        if (kc < 30) {
            int nstage = stage + 2;
            if (nstage >= 3) nstage -= 3;
            uint32_t dstb = sb + nstage * STG;
            CP16(dstb + OAH + sto, gah + (kc + 2) * 16);
            CP16(dstb + OAL + sto, gal + (kc + 2) * 16);
            CP16(dstb + OBH + sto, gbh + (kc + 2) * 16);
            CP16(dstb + OBL + sto, gbl + (kc + 2) * 16);
        }
        asm volatile("cp.async.commit_group;" ::: "memory");

        uint32_t sbase = sb + stage * STG;
        uint32_t aHi[4][4], aLo[4][4];
#pragma unroll
        for (int mt = 0; mt < 4; mt++) {
            LDSM4(aHi[mt][0], aHi[mt][1], aHi[mt][2], aHi[mt][3],
                  sbase + OAH + a_off + mt * 16 * 48);
            LDSM4(aLo[mt][0], aLo[mt][1], aLo[mt][2], aLo[mt][3],
                  sbase + OAL + a_off + mt * 16 * 48);
        }
#pragma unroll
        for (int p = 0; p < 2; p++) {
            uint32_t bh0, bh1, bh2, bh3, bl0, bl1, bl2, bl3;
            LDSM4(bh0, bh1, bh2, bh3, sbase + OBH + b_off + p * 16 * 48);
            LDSM4(bl0, bl1, bl2, bl3, sbase + OBL + b_off + p * 16 * 48);
#pragma unroll
            for (int mt = 0; mt < 4; mt++) {
                MMA16816(acc[mt][p * 2], aHi[mt][0], aHi[mt][1], aHi[mt][2], aHi[mt][3],
                         bh0, bh1);
                MMA16816(acc[mt][p * 2], aHi[mt][0], aHi[mt][1], aHi[mt][2], aHi[mt][3],
                         bl0, bl1);
                MMA16816(acc[mt][p * 2], aLo[mt][0], aLo[mt][1], aLo[mt][2], aLo[mt][3],
                         bh0, bh1);
                MMA16816(acc[mt][p * 2 + 1], aHi[mt][0], aHi[mt][1], aHi[mt][2], aHi[mt][3],
                         bh2, bh3);
                MMA16816(acc[mt][p * 2 + 1], aHi[mt][0], aHi[mt][1], aHi[mt][2], aHi[mt][3],
                         bl2, bl3);
                MMA16816(acc[mt][p * 2 + 1], aLo[mt][0], aLo[mt][1], aLo[mt][2], aLo[mt][3],
                         bh2, bh3);
            }
        }
        if (++stage == 3) stage = 0;
    }

#pragma unroll
    for (int mt = 0; mt < 4; mt++)
#pragma unroll
        for (int nt = 0; nt < 4; nt++) {
            int r0 = m0 + mb + mt * 16 + (lane >> 2);
            int col = n0 + nb + nt * 8 + (lane & 3) * 2;
            float2 bb = *(const float2*)(bias + col);
            float2 v0 = make_float2(acc[mt][nt][0] + bb.x, acc[mt][nt][1] + bb.y);
            float2 v1 = make_float2(acc[mt][nt][2] + bb.x, acc[mt][nt][3] + bb.y);
            *(float2*)(out + ((size_t)(r0 & 15) * 128 + (r0 >> 4)) * 32000 + col) = v0;
            int r1 = r0 + 8;
            *(float2*)(out + ((size_t)(r1 & 15) * 128 + (r1 >> 4)) * 32000 + col) = v1;
        }
}

extern "C" void kernel_launch(void* const* d_in, const int* in_sizes, int n_in,
                              void* d_out, int out_size) {
    const int* tokens = (const int*)d_in[0];
    const float* memory = (const float*)d_in[1];
    const float* h0 = (const float*)d_in[2];
    const float* c0 = (const float*)d_in[3];
    const float* emb = (const float*)d_in[4];
    const float* Wk = (const float*)d_in[5];
    const float* Wr = (const float*)d_in[6];
    const float* bvec = (const float*)d_in[7];
    const float* Wm = (const float*)d_in[8];
    const float* Wa = (const float*)d_in[9];
    const float* Wf = (const float*)d_in[10];
    const float* bf = (const float*)d_in[11];
    float* out = (float*)d_out;

    cudaFuncSetAttribute(vocab_gemm, cudaFuncAttributeMaxDynamicSharedMemorySize, 74752);
    cudaFuncSetAttribute(fused_loop, cudaFuncAttributeMaxDynamicSharedMemorySize, 230400);

    p0_init<<<32, 256>>>(h0);
    p4_bsplit<<<dim3(1000, 16), dim3(32, 8)>>>(Wf);
    sgemm_k<0><<<dim3(4, 16), 256>>>(memory, Wm, nullptr, nullptr, 512);
    sgemm_k<1><<<dim3(16, 16), 256>>>(emb, Wk, bvec, tokens, 256);

    fused_loop<<<128, 256, 230400>>>(memory, Wk, Wr, Wa, c0);

    vocab_gemm<<<dim3(250, 16), 256, 74752>>>(bf, out);
}

// round 11
// speedup vs baseline: 2.9738x; 1.0562x over previous
#include <cuda_runtime.h>
#include <cuda_bf16.h>
#include <math.h>
#include <stdint.h>

// B=16 T=128 S=128 V=32000 E=256 F=512 ; u=[attn;h] (1024), gates 4F=2048
__device__ float g_keys[2048 * 512];     // [b*128+s][e]
__device__ float g_Zp[128 * 2048 * 16];  // [t][c*16+nl][b]
__device__ float g_ut[2][1024 * 16];     // u transposed [k][b], parity buffered
__device__ float g_h[16 * 512];
__device__ float g_scores[16 * 128];     // [b][s]
__device__ float g_ctxT[512 * 16];       // ctx transposed [d][b]
__device__ unsigned g_barc;
__device__ unsigned g_vq;                // vocab tile queue
// bf16 split operands for tensor-core vocab GEMM
__device__ __nv_bfloat16 g_Ahi[2048 * 512];
__device__ __nv_bfloat16 g_Alo[2048 * 512];
__device__ __nv_bfloat16 g_Bhi[32000 * 512];  // Wf^T : [v][k], K contiguous
__device__ __nv_bfloat16 g_Blo[32000 * 512];

__device__ __forceinline__ uint32_t smem_u32(const void* p) {
    uint32_t a;
    asm("{ .reg .u64 t; cvta.to.shared.u64 t, %1; cvt.u32.u64 %0, t; }" : "=r"(a) : "l"(p));
    return a;
}

#define LDSM4(r0, r1, r2, r3, addr) \
    asm volatile("ldmatrix.sync.aligned.m8n8.x4.shared.b16 {%0,%1,%2,%3}, [%4];" \
                 : "=r"(r0), "=r"(r1), "=r"(r2), "=r"(r3) : "r"(addr))

#define MMA16816(d, a0, a1, a2, a3, b0, b1) \
    asm volatile("mma.sync.aligned.m16n8k16.row.col.f32.bf16.bf16.f32 " \
                 "{%0,%1,%2,%3}, {%4,%5,%6,%7}, {%8,%9}, {%0,%1,%2,%3};" \
                 : "+f"((d)[0]), "+f"((d)[1]), "+f"((d)[2]), "+f"((d)[3]) \
                 : "r"(a0), "r"(a1), "r"(a2), "r"(a3), "r"(b0), "r"(b1))

#define CP16(sa, gp) \
    asm volatile("cp.async.cg.shared.global [%0], [%1], 16;" :: "r"(sa), "l"(gp) : "memory")

// -------- grid barrier over the 128 WORKER CTAs (4 bars per step) --------
__device__ __forceinline__ void gbar(unsigned gen) {
    __syncthreads();
    if (threadIdx.x == 0) {
        asm volatile("red.release.gpu.add.u32 [%0], 1;" :: "l"(&g_barc) : "memory");
        unsigned tgt = gen * 128u, v;
        do {
            asm volatile("ld.acquire.gpu.u32 %0, [%1];" : "=r"(v) : "l"(&g_barc) : "memory");
        } while (v < tgt);
    }
    __syncthreads();
}

__global__ void p0_init(const float* __restrict__ h0) {
    int idx = blockIdx.x * 256 + threadIdx.x;
    if (idx == 0) { g_barc = 0u; g_vq = 0u; }
    if (idx < 8192) {
        g_ut[0][idx] = 0.f;  // attn half (k<512) = 0
        int b = idx >> 9, j = idx & 511;
        g_ut[0][(512 + j) * 16 + b] = h0[idx];
    }
}

// Wf [512][32000] -> bf16 hi/lo transposed [32000][512]
__global__ void p4_bsplit(const float* __restrict__ Wf) {
    __shared__ float ts[32][33];
    int v0 = blockIdx.x * 32, k0 = blockIdx.y * 32;
    int tx = threadIdx.x, ty = threadIdx.y;
#pragma unroll
    for (int i = 0; i < 4; i++)
        ts[ty + i * 8][tx] = Wf[(size_t)(k0 + ty + i * 8) * 32000 + v0 + tx];
    __syncthreads();
#pragma unroll
    for (int i = 0; i < 4; i++) {
        int r = ty + i * 8;
        float x = ts[tx][r];
        __nv_bfloat16 hi = __float2bfloat16(x);
        g_Bhi[(size_t)(v0 + r) * 512 + k0 + tx] = hi;
        g_Blo[(size_t)(v0 + r) * 512 + k0 + tx] = __float2bfloat16(x - __bfloat162float(hi));
    }
}

// 128x128x8 double-buffered fp32 SGEMM (precompute only)
// MODE0: keys=memory@Wm (N=512,K=512)  MODE1: Zp=emb[tok]@Wk[:256]+b (N=2048,K=256)
template <int MODE>
__global__ __launch_bounds__(256, 2)
void sgemm_k(const float* __restrict__ A, const float* __restrict__ Bm,
             const float* __restrict__ bias, const int* __restrict__ tokens, int K) {
    const int N = (MODE == 0) ? 512 : 2048;
    __shared__ float As[2][8][128], Bs[2][8][128];
    int tid = threadIdx.x, m0 = blockIdx.y * 128, n0 = blockIdx.x * 128;
    int lm = tid >> 1, lk = (tid & 1) * 4;
    const float* Arow;
    if (MODE == 1) {
        int m = m0 + lm;
        Arow = A + (size_t)tokens[(m & 15) * 128 + (m >> 4)] * K + lk;
    } else {
        Arow = A + (size_t)(m0 + lm) * K + lk;
    }
    int bk = tid >> 5, bn = (tid & 31) * 4;
    const float* Bptr = Bm + (size_t)bk * N + n0 + bn;

    float acc[8][8];
#pragma unroll
    for (int i = 0; i < 8; i++)
#pragma unroll
        for (int j = 0; j < 8; j++) acc[i][j] = 0.f;

    {
        float4 a4 = *(const float4*)Arow;
        float4 b4 = *(const float4*)Bptr;
        As[0][lk][lm] = a4.x; As[0][lk + 1][lm] = a4.y;
        As[0][lk + 2][lm] = a4.z; As[0][lk + 3][lm] = a4.w;
        *(float4*)&Bs[0][bk][bn] = b4;
    }
    __syncthreads();

    int nst = K / 8, buf = 0, tx = tid & 15, ty = tid >> 4;
    for (int ks = 1; ks <= nst; ks++) {
        float4 na, nb;
        if (ks < nst) {
            na = *(const float4*)(Arow + ks * 8);
            nb = *(const float4*)(Bptr + (size_t)ks * 8 * N);
        }
#pragma unroll
        for (int kk = 0; kk < 8; kk++) {
            float a[8], b[8];
            *(float4*)&a[0] = *(const float4*)&As[buf][kk][ty * 4];
            *(float4*)&a[4] = *(const float4*)&As[buf][kk][64 + ty * 4];
            *(float4*)&b[0] = *(const float4*)&Bs[buf][kk][tx * 4];
            *(float4*)&b[4] = *(const float4*)&Bs[buf][kk][64 + tx * 4];
#pragma unroll
            for (int i = 0; i < 8; i++)
#pragma unroll
                for (int j = 0; j < 8; j++) acc[i][j] += a[i] * b[j];
        }
        if (ks < nst) {
            buf ^= 1;
            As[buf][lk][lm] = na.x; As[buf][lk + 1][lm] = na.y;
            As[buf][lk + 2][lm] = na.z; As[buf][lk + 3][lm] = na.w;
            *(float4*)&Bs[buf][bk][bn] = nb;
            __syncthreads();
        }
    }

#pragma unroll
    for (int i = 0; i < 8; i++) {
        int mrow = m0 + ((i < 4) ? (ty * 4 + i) : (64 + ty * 4 + i - 4));
#pragma unroll
        for (int jh = 0; jh < 2; jh++) {
            int ncol = n0 + jh * 64 + tx * 4;
            if (MODE == 0) {
                float4 v = make_float4(acc[i][jh * 4], acc[i][jh * 4 + 1],
                                       acc[i][jh * 4 + 2], acc[i][jh * 4 + 3]);
                *(float4*)(g_keys + (size_t)mrow * 512 + ncol) = v;
            } else {
#pragma unroll
                for (int jj = 0; jj < 4; jj++) {
                    int n = ncol + jj;
                    int nl2 = (n >> 9) * 4 + (n & 3);
                    g_Zp[((size_t)(mrow >> 4) * 2048 + ((n & 511) >> 2) * 16 + nl2) * 16 +
                         (mrow & 15)] = acc[i][jh * 4 + jj] + bias[n];
                }
            }
        }
    }
}

// -------- one 128x128 vocab tile (HMMA hi/lo split, 3-stage cp.async) --------
__device__ __forceinline__ void vocab_tile(char* smb, uint32_t sb, int xt, int yt,
                                           const float* __restrict__ bias,
                                           float* __restrict__ out) {
    const int tid = threadIdx.x, wid = tid >> 5, lane = tid & 31;
    const int n0 = xt * 128, m0 = yt * 128;
    const int STG = 24576;
    const int OAH = 0, OAL = 6144, OBH = 12288, OBL = 18432;
    int mb = (wid >> 2) * 64, nb = (wid & 3) * 32;
    int row = tid >> 1, half = tid & 1;

    float acc[4][4][4];
#pragma unroll
    for (int i = 0; i < 4; i++)
#pragma unroll
        for (int j = 0; j < 4; j++)
#pragma unroll
            for (int q = 0; q < 4; q++) acc[i][j][q] = 0.f;

    const __nv_bfloat16* gah = g_Ahi + (size_t)(m0 + row) * 512 + half * 8;
    const __nv_bfloat16* gal = g_Alo + (size_t)(m0 + row) * 512 + half * 8;
    const __nv_bfloat16* gbh = g_Bhi + (size_t)(n0 + row) * 512 + half * 8;
    const __nv_bfloat16* gbl = g_Blo + (size_t)(n0 + row) * 512 + half * 8;
    uint32_t sto = row * 48 + half * 16;

#pragma unroll
    for (int pc = 0; pc < 2; pc++) {
        uint32_t dstb = sb + pc * STG;
        CP16(dstb + OAH + sto, gah + pc * 16);
        CP16(dstb + OAL + sto, gal + pc * 16);
        CP16(dstb + OBH + sto, gbh + pc * 16);
        CP16(dstb + OBL + sto, gbl + pc * 16);
        asm volatile("cp.async.commit_group;" ::: "memory");
    }

    uint32_t a_off = (uint32_t)((mb + (lane & 15)) * 48 + (lane >> 4) * 16);
    uint32_t b_off = (uint32_t)((nb + (lane & 7) + ((lane >> 4) & 1) * 8) * 48 +
                                ((lane >> 3) & 1) * 16);

    int stage = 0;
    for (int kc = 0; kc < 32; kc++) {
        asm volatile("cp.async.wait_group 1;" ::: "memory");
        __syncthreads();
        if (kc < 30) {
            int nstage = stage + 2;
            if (nstage >= 3) nstage -= 3;
            uint32_t dstb = sb + nstage * STG;
            CP16(dstb + OAH + sto, gah + (kc + 2) * 16);
            CP16(dstb + OAL + sto, gal + (kc + 2) * 16);
            CP16(dstb + OBH + sto, gbh + (kc + 2) * 16);
            CP16(dstb + OBL + sto, gbl + (kc + 2) * 16);
        }
        asm volatile("cp.async.commit_group;" ::: "memory");

        uint32_t sbase = sb + stage * STG;
        uint32_t aHi[4][4], aLo[4][4];
#pragma unroll
        for (int mt = 0; mt < 4; mt++) {
            LDSM4(aHi[mt][0], aHi[mt][1], aHi[mt][2], aHi[mt][3],
                  sbase + OAH + a_off + mt * 16 * 48);
            LDSM4(aLo[mt][0], aLo[mt][1], aLo[mt][2], aLo[mt][3],
                  sbase + OAL + a_off + mt * 16 * 48);
        }
#pragma unroll
        for (int p = 0; p < 2; p++) {
            uint32_t bh0, bh1, bh2, bh3, bl0, bl1, bl2, bl3;
            LDSM4(bh0, bh1, bh2, bh3, sbase + OBH + b_off + p * 16 * 48);
            LDSM4(bl0, bl1, bl2, bl3, sbase + OBL + b_off + p * 16 * 48);
#pragma unroll
            for (int mt = 0; mt < 4; mt++) {
                MMA16816(acc[mt][p * 2], aHi[mt][0], aHi[mt][1], aHi[mt][2], aHi[mt][3],
                         bh0, bh1);
                MMA16816(acc[mt][p * 2], aHi[mt][0], aHi[mt][1], aHi[mt][2], aHi[mt][3],
                         bl0, bl1);
                MMA16816(acc[mt][p * 2], aLo[mt][0], aLo[mt][1], aLo[mt][2], aLo[mt][3],
                         bh0, bh1);
                MMA16816(acc[mt][p * 2 + 1], aHi[mt][0], aHi[mt][1], aHi[mt][2], aHi[mt][3],
                         bh2, bh3);
                MMA16816(acc[mt][p * 2 + 1], aHi[mt][0], aHi[mt][1], aHi[mt][2], aHi[mt][3],
                         bl2, bl3);
                MMA16816(acc[mt][p * 2 + 1], aLo[mt][0], aLo[mt][1], aLo[mt][2], aLo[mt][3],
                         bh2, bh3);
            }
        }
        if (++stage == 3) stage = 0;
    }
    __syncthreads();  // all reads of this tile's smem done before next tile reuses it

#pragma unroll
    for (int mt = 0; mt < 4; mt++)
#pragma unroll
        for (int nt = 0; nt < 4; nt++) {
            int r0 = m0 + mb + mt * 16 + (lane >> 2);
            int col = n0 + nb + nt * 8 + (lane & 3) * 2;
            float2 bb = *(const float2*)(bias + col);
            float2 v0 = make_float2(acc[mt][nt][0] + bb.x, acc[mt][nt][1] + bb.y);
            float2 v1 = make_float2(acc[mt][nt][2] + bb.x, acc[mt][nt][3] + bb.y);
            *(float2*)(out + ((size_t)(r0 & 15) * 128 + (r0 >> 4)) * 32000 + col) = v0;
            int r1 = r0 + 8;
            *(float2*)(out + ((size_t)(r1 & 15) * 128 + (r1 >> 4)) * 32000 + col) = v1;
        }
}

// ================= fused persistent kernel: 148 CTAs, 256 threads =================
// CTAs 0..127: recurrence (exact r8 arithmetic). CTAs 128..147: vocab helpers.
// After the loop, everyone drains the vocab tile queue.
// smem floats: sWp 16384 | sU 16384 | sWa 4096 | sPS 4096 | sZ 256 | sKeys 8192 | sMem 8192
#define O_WP 0
#define O_U 16384
#define O_WA 32768
#define O_PS 36864
#define O_Z 40960
#define O_KEYS 41216
#define O_MEM 49408
__global__ __launch_bounds__(256) void fused_all(const float* __restrict__ memory,
                                                 const float* __restrict__ Wk,
                                                 const float* __restrict__ Wr,
                                                 const float* __restrict__ Wa,
                                                 const float* __restrict__ c0,
                                                 const float* __restrict__ bf,
                                                 float* __restrict__ out) {
    extern __shared__ float sm[];
    const int c = blockIdx.x, tid = threadIdx.x;
    __shared__ unsigned s_tile;

    if (c < 128) {
        float* sWp = sm + O_WP;
        float* sU = sm + O_U;
        float* sWa = sm + O_WA;
        float* sPS = sm + O_PS;
        float* sZ = sm + O_Z;
        float* sKeys = sm + O_KEYS;
        float* sMem = sm + O_MEM;
        const int ab = c >> 3;
        const int s0 = (c & 7) * 16;
        const int d0 = (c & 7) * 64;

        for (int it = 0; it < 64; it++) {
            int idx = tid + it * 256;
            int k = idx >> 4, nl = idx & 15;
            int n = (nl >> 2) * 512 + c * 4 + (nl & 3);
            sWp[idx] = (k < 512) ? Wk[(size_t)(256 + k) * 2048 + n]
                                 : Wr[(size_t)(k - 512) * 2048 + n];
        }
        for (int it = 0; it < 16; it++) {
            int idx = tid + it * 256;
            sWa[idx] = Wa[(size_t)(idx >> 2) * 512 + c * 4 + (idx & 3)];
        }
        for (int i = tid; i < 8192; i += 256) {
            int r = i >> 9, k = i & 511;
            sKeys[i] = g_keys[((size_t)ab * 128 + s0 + r) * 512 + k];
        }
        for (int i = tid; i < 8192; i += 256) {
            int s = i >> 6, dl = i & 63;
            sMem[i] = memory[((size_t)ab * 128 + s) * 512 + d0 + dl];
        }
        const int jl = tid & 3, bb = tid >> 2;
        float creg = 0.f;
        if (tid < 64) creg = c0[bb * 512 + c * 4 + jl];
        __syncthreads();

        unsigned gen = 0;
        for (int t = 0; t < 128; t++) {
            int cur = t & 1, nx = cur ^ 1;
            // ---------- phase 1 ----------
            const int nlr = tid >> 4, br = tid & 15;
            float zpre = __ldcg(g_Zp + ((size_t)t * 2048 + c * 16 + nlr) * 16 + br);
            {
                const float4* gu = (const float4*)g_ut[cur];
                float4* su4 = (float4*)sU;
#pragma unroll
                for (int i = 0; i < 16; i++) su4[tid + i * 256] = __ldcg(gu + tid + i * 256);
            }
            __syncthreads();
            {
                int nl = tid & 15, kc = tid >> 4;
                const float* wp = sWp + kc * 64 * 16 + nl;
                const float4* up = (const float4*)(sU + kc * 64 * 16);
                float acc[16];
#pragma unroll
                for (int i = 0; i < 16; i++) acc[i] = 0.f;
#pragma unroll 4
                for (int i = 0; i < 64; i++) {
                    float w = wp[i * 16];
                    float4 u0 = up[i * 4], u1 = up[i * 4 + 1];
                    float4 u2 = up[i * 4 + 2], u3 = up[i * 4 + 3];
                    acc[0] += w * u0.x; acc[1] += w * u0.y; acc[2] += w * u0.z; acc[3] += w * u0.w;
                    acc[4] += w * u1.x; acc[5] += w * u1.y; acc[6] += w * u1.z; acc[7] += w * u1.w;
                    acc[8] += w * u2.x; acc[9] += w * u2.y; acc[10] += w * u2.z; acc[11] += w * u2.w;
                    acc[12] += w * u3.x; acc[13] += w * u3.y; acc[14] += w * u3.z; acc[15] += w * u3.w;
                }
#pragma unroll
                for (int b = 0; b < 16; b++) sPS[(kc * 16 + nl) * 16 + b] = acc[b];
            }
            __syncthreads();
            {
                float z = zpre;
#pragma unroll
                for (int q = 0; q < 16; q++) z += sPS[(q * 16 + nlr) * 16 + br];
                sZ[nlr * 16 + br] = z;
            }
            __syncthreads();
            if (tid < 64) {
                float zi = sZ[jl * 16 + bb], zf = sZ[(4 + jl) * 16 + bb];
                float zg = sZ[(8 + jl) * 16 + bb], zo = sZ[(12 + jl) * 16 + bb];
                float si = 1.f / (1.f + expf(-zi)), sf = 1.f / (1.f + expf(-zf));
                float so = 1.f / (1.f + expf(-zo));
                creg = sf * creg + si * tanhf(zg);
                float hh = so * tanhf(creg);
                int j = c * 4 + jl;
                g_h[bb * 512 + j] = hh;
                g_ut[nx][(512 + j) * 16 + bb] = hh;
            }
            gbar(++gen);

            // ---------- phase 2a ----------
            {
                float* h_sh = sPS;
                h_sh[tid] = __ldcg(g_h + ab * 512 + tid);
                h_sh[tid + 256] = __ldcg(g_h + ab * 512 + tid + 256);
                __syncthreads();
                if (tid < 64) {
                    int s_l = tid >> 2, q = tid & 3;
                    const float4* kp = (const float4*)(sKeys + s_l * 512 + q * 128);
                    const float* hp = h_sh + q * 128;
                    float a = 0.f;
#pragma unroll 8
                    for (int i = 0; i < 32; i++) {
                        float4 kv = kp[i];
                        a += kv.x * hp[i * 4] + kv.y * hp[i * 4 + 1] +
                             kv.z * hp[i * 4 + 2] + kv.w * hp[i * 4 + 3];
                    }
                    a += __shfl_xor_sync(0xffffffffu, a, 1);
                    a += __shfl_xor_sync(0xffffffffu, a, 2);
                    if (q == 0) g_scores[ab * 128 + s0 + s_l] = a;
                }
            }
            gbar(++gen);

            // ---------- phase 2b ----------
            {
                float* w_sh = sPS + 512;
                float* red = sPS + 640;
                float* ctxp = sPS + 1024;
                if (tid < 128) w_sh[tid] = __ldcg(g_scores + ab * 128 + tid);
                __syncthreads();
                float sc = (tid < 128) ? w_sh[tid] : -1e30f;
                float mx = sc;
#pragma unroll
                for (int o = 16; o >= 1; o >>= 1)
                    mx = fmaxf(mx, __shfl_xor_sync(0xffffffffu, mx, o));
                if ((tid & 31) == 0) red[tid >> 5] = mx;
                __syncthreads();
                float gmx = fmaxf(fmaxf(red[0], red[1]), fmaxf(red[2], red[3]));
                __syncthreads();
                float e = (tid < 128) ? expf(sc - gmx) : 0.f;
                float smv = e;
#pragma unroll
                for (int o = 16; o >= 1; o >>= 1)
                    smv += __shfl_xor_sync(0xffffffffu, smv, o);
                if ((tid & 31) == 0) red[tid >> 5] = smv;
                __syncthreads();
                float gsum = red[0] + red[1] + red[2] + red[3];
                if (tid < 128) w_sh[tid] = e / gsum;
                __syncthreads();
                if (tid < 64) {
                    int sq = tid >> 4, d4l = tid & 15;
                    const float* mp = sMem + sq * 32 * 64;
                    float4 ca = make_float4(0.f, 0.f, 0.f, 0.f);
#pragma unroll 4
                    for (int i = 0; i < 32; i++) {
                        float w = w_sh[sq * 32 + i];
                        float4 mv = *(const float4*)(mp + i * 64 + d4l * 4);
                        ca.x += w * mv.x; ca.y += w * mv.y;
                        ca.z += w * mv.z; ca.w += w * mv.w;
                    }
                    *(float4*)&ctxp[sq * 64 + d4l * 4] = ca;
                }
                __syncthreads();
                if (tid < 64) {
                    float v = ctxp[tid] + ctxp[64 + tid] + ctxp[128 + tid] + ctxp[192 + tid];
                    g_ctxT[(d0 + tid) * 16 + ab] = v;
                }
            }
            gbar(++gen);

            // ---------- phase 3 ----------
            {
                const float4* hsrc = (const float4*)(g_ut[nx] + 512 * 16);
                const float4* csrc = (const float4*)g_ctxT;
                float4* du = (float4*)sU;
#pragma unroll
                for (int i = 0; i < 8; i++) du[tid + i * 256] = __ldcg(hsrc + tid + i * 256);
#pragma unroll
                for (int i = 0; i < 8; i++)
                    du[2048 + tid + i * 256] = __ldcg(csrc + tid + i * 256);
            }
            __syncthreads();
            {
                int b = tid & 15, kq = tid >> 4;
                const float* uc = sU + kq * 64 * 16 + b;
                const float4* wv = (const float4*)(sWa + kq * 64 * 4);
                float a0 = 0.f, a1 = 0.f, a2 = 0.f, a3 = 0.f;
#pragma unroll 4
                for (int i = 0; i < 64; i++) {
                    float u = uc[i * 16];
                    float4 w4 = wv[i];
                    a0 += u * w4.x; a1 += u * w4.y; a2 += u * w4.z; a3 += u * w4.w;
                }
                sPS[(kq * 4 + 0) * 16 + b] = a0;
                sPS[(kq * 4 + 1) * 16 + b] = a1;
                sPS[(kq * 4 + 2) * 16 + b] = a2;
                sPS[(kq * 4 + 3) * 16 + b] = a3;
            }
            __syncthreads();
            if (tid < 64) {
                int cl = tid >> 4, b2 = tid & 15;
                float v = 0.f;
#pragma unroll
                for (int q = 0; q < 16; q++) v += sPS[(q * 4 + cl) * 16 + b2];
                int col = c * 4 + cl;
                g_ut[nx][col * 16 + b2] = v;
                __nv_bfloat16 hi = __float2bfloat16(v);
                size_t row = (size_t)t * 16 + b2;
                g_Ahi[row * 512 + col] = hi;
                g_Alo[row * 512 + col] = __float2bfloat16(v - __bfloat162float(hi));
            }
            gbar(++gen);
        }
    }

    // ================= vocab tile queue (all 148 CTAs) =================
    char* smb = (char*)(((uintptr_t)sm + 1023) & ~(uintptr_t)1023);
    uint32_t sbv = smem_u32(smb);
    for (;;) {
        __syncthreads();
        if (tid == 0) s_tile = atomicAdd(&g_vq, 1u);
        __syncthreads();
        unsigned i = s_tile;
        if (i >= 4000u) break;
        int yt = (int)(i / 250u), xt = (int)(i - (unsigned)yt * 250u);
        if (tid == 0) {
            unsigned need = (unsigned)(yt * 8 + 8);   // steps whose attns rows tile yt reads
            unsigned tgt = 512u * need, v;            // 4 bars/step * 128 CTA arrivals
            do {
                asm volatile("ld.acquire.gpu.u32 %0, [%1];" : "=r"(v) : "l"(&g_barc)
                             : "memory");
            } while (v < tgt);
        }
        __syncthreads();
        vocab_tile(smb, sbv, xt, yt, bf, out);
    }
}

extern "C" void kernel_launch(void* const* d_in, const int* in_sizes, int n_in,
                              void* d_out, int out_size) {
    const int* tokens = (const int*)d_in[0];
    const float* memory = (const float*)d_in[1];
    const float* h0 = (const float*)d_in[2];
    const float* c0 = (const float*)d_in[3];
    const float* emb = (const float*)d_in[4];
    const float* Wk = (const float*)d_in[5];
    const float* Wr = (const float*)d_in[6];
    const float* bvec = (const float*)d_in[7];
    const float* Wm = (const float*)d_in[8];
    const float* Wa = (const float*)d_in[9];
    const float* Wf = (const float*)d_in[10];
    const float* bf = (const float*)d_in[11];
    float* out = (float*)d_out;

    cudaFuncSetAttribute(fused_all, cudaFuncAttributeMaxDynamicSharedMemorySize, 231424);

    p0_init<<<32, 256>>>(h0);
    p4_bsplit<<<dim3(1000, 16), dim3(32, 8)>>>(Wf);
    sgemm_k<0><<<dim3(4, 16), 256>>>(memory, Wm, nullptr, nullptr, 512);
    sgemm_k<1><<<dim3(16, 16), 256>>>(emb, Wk, bvec, tokens, 256);

    fused_all<<<148, 256, 231424>>>(memory, Wk, Wr, Wa, c0, bf, out);
}

// round 12
// speedup vs baseline: 3.2021x; 1.0768x over previous
#include <cuda_runtime.h>
#include <cuda_bf16.h>
#include <cuda_fp16.h>
#include <math.h>
#include <stdint.h>

// B=16 T=128 S=128 V=32000 E=256 F=512 ; u=[attn;h] (1024), gates 4F=2048
__device__ float g_keys[2048 * 512];     // [b*128+s][e]
__device__ float g_Zp[128 * 2048 * 16];  // [t][c*16+nl][b]
__device__ float g_ut[2][1024 * 16];     // u transposed [k][b], parity buffered
__device__ float g_h[16 * 512];
__device__ float g_scores[16 * 128];     // [b][s]
__device__ float g_ctxT[512 * 16];       // ctx transposed [d][b]
__device__ unsigned g_barc;
__device__ unsigned g_vq;                // vocab tile queue
// fp16 operands for tensor-core vocab GEMM: A rounded, B split hi/lo
__device__ __half g_Af16[2048 * 512];
__device__ __half g_Bhi[32000 * 512];    // Wf^T : [v][k], K contiguous
__device__ __half g_Blo[32000 * 512];

__device__ __forceinline__ uint32_t smem_u32(const void* p) {
    uint32_t a;
    asm("{ .reg .u64 t; cvta.to.shared.u64 t, %1; cvt.u32.u64 %0, t; }" : "=r"(a) : "l"(p));
    return a;
}

#define LDSM4(r0, r1, r2, r3, addr) \
    asm volatile("ldmatrix.sync.aligned.m8n8.x4.shared.b16 {%0,%1,%2,%3}, [%4];" \
                 : "=r"(r0), "=r"(r1), "=r"(r2), "=r"(r3) : "r"(addr))

#define MMA16816(d, a0, a1, a2, a3, b0, b1) \
    asm volatile("mma.sync.aligned.m16n8k16.row.col.f32.f16.f16.f32 " \
                 "{%0,%1,%2,%3}, {%4,%5,%6,%7}, {%8,%9}, {%0,%1,%2,%3};" \
                 : "+f"((d)[0]), "+f"((d)[1]), "+f"((d)[2]), "+f"((d)[3]) \
                 : "r"(a0), "r"(a1), "r"(a2), "r"(a3), "r"(b0), "r"(b1))

#define CP16(sa, gp) \
    asm volatile("cp.async.cg.shared.global [%0], [%1], 16;" :: "r"(sa), "l"(gp) : "memory")

// -------- grid barrier over the 128 WORKER CTAs (4 bars per step) --------
__device__ __forceinline__ void gbar(unsigned gen) {
    __syncthreads();
    if (threadIdx.x == 0) {
        asm volatile("red.release.gpu.add.u32 [%0], 1;" :: "l"(&g_barc) : "memory");
        unsigned tgt = gen * 128u, v;
        do {
            asm volatile("ld.acquire.gpu.u32 %0, [%1];" : "=r"(v) : "l"(&g_barc) : "memory");
        } while (v < tgt);
    }
    __syncthreads();
}

__global__ void p0_init(const float* __restrict__ h0) {
    int idx = blockIdx.x * 256 + threadIdx.x;
    if (idx == 0) { g_barc = 0u; g_vq = 0u; }
    if (idx < 8192) {
        g_ut[0][idx] = 0.f;  // attn half (k<512) = 0
        int b = idx >> 9, j = idx & 511;
        g_ut[0][(512 + j) * 16 + b] = h0[idx];
    }
}

// Wf [512][32000] -> fp16 hi/lo transposed [32000][512]
__global__ void p4_bsplit(const float* __restrict__ Wf) {
    __shared__ float ts[32][33];
    int v0 = blockIdx.x * 32, k0 = blockIdx.y * 32;
    int tx = threadIdx.x, ty = threadIdx.y;
#pragma unroll
    for (int i = 0; i < 4; i++)
        ts[ty + i * 8][tx] = Wf[(size_t)(k0 + ty + i * 8) * 32000 + v0 + tx];
    __syncthreads();
#pragma unroll
    for (int i = 0; i < 4; i++) {
        int r = ty + i * 8;
        float x = ts[tx][r];
        __half hi = __float2half_rn(x);
        g_Bhi[(size_t)(v0 + r) * 512 + k0 + tx] = hi;
        g_Blo[(size_t)(v0 + r) * 512 + k0 + tx] = __float2half_rn(x - __half2float(hi));
    }
}

// 128x128x8 double-buffered fp32 SGEMM (precompute only)
// MODE0: keys=memory@Wm (N=512,K=512)  MODE1: Zp=emb[tok]@Wk[:256]+b (N=2048,K=256)
template <int MODE>
__global__ __launch_bounds__(256, 2)
void sgemm_k(const float* __restrict__ A, const float* __restrict__ Bm,
             const float* __restrict__ bias, const int* __restrict__ tokens, int K) {
    const int N = (MODE == 0) ? 512 : 2048;
    __shared__ float As[2][8][128], Bs[2][8][128];
    int tid = threadIdx.x, m0 = blockIdx.y * 128, n0 = blockIdx.x * 128;
    int lm = tid >> 1, lk = (tid & 1) * 4;
    const float* Arow;
    if (MODE == 1) {
        int m = m0 + lm;
        Arow = A + (size_t)tokens[(m & 15) * 128 + (m >> 4)] * K + lk;
    } else {
        Arow = A + (size_t)(m0 + lm) * K + lk;
    }
    int bk = tid >> 5, bn = (tid & 31) * 4;
    const float* Bptr = Bm + (size_t)bk * N + n0 + bn;

    float acc[8][8];
#pragma unroll
    for (int i = 0; i < 8; i++)
#pragma unroll
        for (int j = 0; j < 8; j++) acc[i][j] = 0.f;

    {
        float4 a4 = *(const float4*)Arow;
        float4 b4 = *(const float4*)Bptr;
        As[0][lk][lm] = a4.x; As[0][lk + 1][lm] = a4.y;
        As[0][lk + 2][lm] = a4.z; As[0][lk + 3][lm] = a4.w;
        *(float4*)&Bs[0][bk][bn] = b4;
    }
    __syncthreads();

    int nst = K / 8, buf = 0, tx = tid & 15, ty = tid >> 4;
    for (int ks = 1; ks <= nst; ks++) {
        float4 na, nb;
        if (ks < nst) {
            na = *(const float4*)(Arow + ks * 8);
            nb = *(const float4*)(Bptr + (size_t)ks * 8 * N);
        }
#pragma unroll
        for (int kk = 0; kk < 8; kk++) {
            float a[8], b[8];
            *(float4*)&a[0] = *(const float4*)&As[buf][kk][ty * 4];
            *(float4*)&a[4] = *(const float4*)&As[buf][kk][64 + ty * 4];
            *(float4*)&b[0] = *(const float4*)&Bs[buf][kk][tx * 4];
            *(float4*)&b[4] = *(const float4*)&Bs[buf][kk][64 + tx * 4];
#pragma unroll
            for (int i = 0; i < 8; i++)
#pragma unroll
                for (int j = 0; j < 8; j++) acc[i][j] += a[i] * b[j];
        }
        if (ks < nst) {
            buf ^= 1;
            As[buf][lk][lm] = na.x; As[buf][lk + 1][lm] = na.y;
            As[buf][lk + 2][lm] = na.z; As[buf][lk + 3][lm] = na.w;
            *(float4*)&Bs[buf][bk][bn] = nb;
            __syncthreads();
        }
    }

#pragma unroll
    for (int i = 0; i < 8; i++) {
        int mrow = m0 + ((i < 4) ? (ty * 4 + i) : (64 + ty * 4 + i - 4));
#pragma unroll
        for (int jh = 0; jh < 2; jh++) {
            int ncol = n0 + jh * 64 + tx * 4;
            if (MODE == 0) {
                float4 v = make_float4(acc[i][jh * 4], acc[i][jh * 4 + 1],
                                       acc[i][jh * 4 + 2], acc[i][jh * 4 + 3]);
                *(float4*)(g_keys + (size_t)mrow * 512 + ncol) = v;
            } else {
#pragma unroll
                for (int jj = 0; jj < 4; jj++) {
                    int n = ncol + jj;
                    int nl2 = (n >> 9) * 4 + (n & 3);
                    g_Zp[((size_t)(mrow >> 4) * 2048 + ((n & 511) >> 2) * 16 + nl2) * 16 +
                         (mrow & 15)] = acc[i][jh * 4 + jj] + bias[n];
                }
            }
        }
    }
}

// -------- one 128x128 vocab tile (fp16 A * fp16 hi/lo B, 3-stage cp.async) --------
__device__ __forceinline__ void vocab_tile(char* smb, uint32_t sb, int xt, int yt,
                                           const float* __restrict__ bias,
                                           float* __restrict__ out) {
    const int tid = threadIdx.x, wid = tid >> 5, lane = tid & 31;
    const int n0 = xt * 128, m0 = yt * 128;
    const int STG = 18432;                       // 3 matrices * 6144
    const int OA = 0, OBH = 6144, OBL = 12288;
    int mb = (wid >> 2) * 64, nb = (wid & 3) * 32;
    int row = tid >> 1, half = tid & 1;

    float acc[4][4][4];
#pragma unroll
    for (int i = 0; i < 4; i++)
#pragma unroll
        for (int j = 0; j < 4; j++)
#pragma unroll
            for (int q = 0; q < 4; q++) acc[i][j][q] = 0.f;

    const __half* ga = g_Af16 + (size_t)(m0 + row) * 512 + half * 8;
    const __half* gbh = g_Bhi + (size_t)(n0 + row) * 512 + half * 8;
    const __half* gbl = g_Blo + (size_t)(n0 + row) * 512 + half * 8;
    uint32_t sto = row * 48 + half * 16;

#pragma unroll
    for (int pc = 0; pc < 2; pc++) {
        uint32_t dstb = sb + pc * STG;
        CP16(dstb + OA + sto, ga + pc * 16);
        CP16(dstb + OBH + sto, gbh + pc * 16);
        CP16(dstb + OBL + sto, gbl + pc * 16);
        asm volatile("cp.async.commit_group;" ::: "memory");
    }

    uint32_t a_off = (uint32_t)((mb + (lane & 15)) * 48 + (lane >> 4) * 16);
    uint32_t b_off = (uint32_t)((nb + (lane & 7) + ((lane >> 4) & 1) * 8) * 48 +
                                ((lane >> 3) & 1) * 16);

    int stage = 0;
    for (int kc = 0; kc < 32; kc++) {
        asm volatile("cp.async.wait_group 1;" ::: "memory");
        __syncthreads();
        if (kc < 30) {
            int nstage = stage + 2;
            if (nstage >= 3) nstage -= 3;
            uint32_t dstb = sb + nstage * STG;
            CP16(dstb + OA + sto, ga + (kc + 2) * 16);
            CP16(dstb + OBH + sto, gbh + (kc + 2) * 16);
            CP16(dstb + OBL + sto, gbl + (kc + 2) * 16);
        }
        asm volatile("cp.async.commit_group;" ::: "memory");

        uint32_t sbase = sb + stage * STG;
        uint32_t aF[4][4];
#pragma unroll
        for (int mt = 0; mt < 4; mt++)
            LDSM4(aF[mt][0], aF[mt][1], aF[mt][2], aF[mt][3],
                  sbase + OA + a_off + mt * 16 * 48);
#pragma unroll
        for (int p = 0; p < 2; p++) {
            uint32_t bh0, bh1, bh2, bh3, bl0, bl1, bl2, bl3;
            LDSM4(bh0, bh1, bh2, bh3, sbase + OBH + b_off + p * 16 * 48);
            LDSM4(bl0, bl1, bl2, bl3, sbase + OBL + b_off + p * 16 * 48);
#pragma unroll
            for (int mt = 0; mt < 4; mt++) {
                MMA16816(acc[mt][p * 2], aF[mt][0], aF[mt][1], aF[mt][2], aF[mt][3],
                         bh0, bh1);
                MMA16816(acc[mt][p * 2], aF[mt][0], aF[mt][1], aF[mt][2], aF[mt][3],
                         bl0, bl1);
                MMA16816(acc[mt][p * 2 + 1], aF[mt][0], aF[mt][1], aF[mt][2], aF[mt][3],
                         bh2, bh3);
                MMA16816(acc[mt][p * 2 + 1], aF[mt][0], aF[mt][1], aF[mt][2], aF[mt][3],
                         bl2, bl3);
            }
        }
        if (++stage == 3) stage = 0;
    }
    __syncthreads();  // all reads of this tile's smem done before next tile reuses it

#pragma unroll
    for (int mt = 0; mt < 4; mt++)
#pragma unroll
        for (int nt = 0; nt < 4; nt++) {
            int r0 = m0 + mb + mt * 16 + (lane >> 2);
            int col = n0 + nb + nt * 8 + (lane & 3) * 2;
            float2 bb = *(const float2*)(bias + col);
            float2 v0 = make_float2(acc[mt][nt][0] + bb.x, acc[mt][nt][1] + bb.y);
            float2 v1 = make_float2(acc[mt][nt][2] + bb.x, acc[mt][nt][3] + bb.y);
            *(float2*)(out + ((size_t)(r0 & 15) * 128 + (r0 >> 4)) * 32000 + col) = v0;
            int r1 = r0 + 8;
            *(float2*)(out + ((size_t)(r1 & 15) * 128 + (r1 >> 4)) * 32000 + col) = v1;
        }
}

// ================= fused persistent kernel: 148 CTAs, 256 threads =================
// CTAs 0..127: recurrence (exact r8 arithmetic). CTAs 128..147: vocab helpers.
// After the loop, everyone drains the vocab tile queue.
#define O_WP 0
#define O_U 16384
#define O_WA 32768
#define O_PS 36864
#define O_Z 40960
#define O_KEYS 41216
#define O_MEM 49408
__global__ __launch_bounds__(256) void fused_all(const float* __restrict__ memory,
                                                 const float* __restrict__ Wk,
                                                 const float* __restrict__ Wr,
                                                 const float* __restrict__ Wa,
                                                 const float* __restrict__ c0,
                                                 const float* __restrict__ bf,
                                                 float* __restrict__ out) {
    extern __shared__ float sm[];
    const int c = blockIdx.x, tid = threadIdx.x;
    __shared__ unsigned s_tile;

    if (c < 128) {
        float* sWp = sm + O_WP;
        float* sU = sm + O_U;
        float* sWa = sm + O_WA;
        float* sPS = sm + O_PS;
        float* sZ = sm + O_Z;
        float* sKeys = sm + O_KEYS;
        float* sMem = sm + O_MEM;
        const int ab = c >> 3;
        const int s0 = (c & 7) * 16;
        const int d0 = (c & 7) * 64;

        for (int it = 0; it < 64; it++) {
            int idx = tid + it * 256;
            int k = idx >> 4, nl = idx & 15;
            int n = (nl >> 2) * 512 + c * 4 + (nl & 3);
            sWp[idx] = (k < 512) ? Wk[(size_t)(256 + k) * 2048 + n]
                                 : Wr[(size_t)(k - 512) * 2048 + n];
        }
        for (int it = 0; it < 16; it++) {
            int idx = tid + it * 256;
            sWa[idx] = Wa[(size_t)(idx >> 2) * 512 + c * 4 + (idx & 3)];
        }
        for (int i = tid; i < 8192; i += 256) {
            int r = i >> 9, k = i & 511;
            sKeys[i] = g_keys[((size_t)ab * 128 + s0 + r) * 512 + k];
        }
        for (int i = tid; i < 8192; i += 256) {
            int s = i >> 6, dl = i & 63;
            sMem[i] = memory[((size_t)ab * 128 + s) * 512 + d0 + dl];
        }
        const int jl = tid & 3, bb = tid >> 2;
        float creg = 0.f;
        if (tid < 64) creg = c0[bb * 512 + c * 4 + jl];
        __syncthreads();

        unsigned gen = 0;
        for (int t = 0; t < 128; t++) {
            int cur = t & 1, nx = cur ^ 1;
            // ---------- phase 1 ----------
            const int nlr = tid >> 4, br = tid & 15;
            float zpre = __ldcg(g_Zp + ((size_t)t * 2048 + c * 16 + nlr) * 16 + br);
            {
                const float4* gu = (const float4*)g_ut[cur];
                float4* su4 = (float4*)sU;
#pragma unroll
                for (int i = 0; i < 16; i++) su4[tid + i * 256] = __ldcg(gu + tid + i * 256);
            }
            __syncthreads();
            {
                int nl = tid & 15, kc = tid >> 4;
                const float* wp = sWp + kc * 64 * 16 + nl;
                const float4* up = (const float4*)(sU + kc * 64 * 16);
                float acc[16];
#pragma unroll
                for (int i = 0; i < 16; i++) acc[i] = 0.f;
#pragma unroll 4
                for (int i = 0; i < 64; i++) {
                    float w = wp[i * 16];
                    float4 u0 = up[i * 4], u1 = up[i * 4 + 1];
                    float4 u2 = up[i * 4 + 2], u3 = up[i * 4 + 3];
                    acc[0] += w * u0.x; acc[1] += w * u0.y; acc[2] += w * u0.z; acc[3] += w * u0.w;
                    acc[4] += w * u1.x; acc[5] += w * u1.y; acc[6] += w * u1.z; acc[7] += w * u1.w;
                    acc[8] += w * u2.x; acc[9] += w * u2.y; acc[10] += w * u2.z; acc[11] += w * u2.w;
                    acc[12] += w * u3.x; acc[13] += w * u3.y; acc[14] += w * u3.z; acc[15] += w * u3.w;
                }
#pragma unroll
                for (int b = 0; b < 16; b++) sPS[(kc * 16 + nl) * 16 + b] = acc[b];
            }
            __syncthreads();
            {
                float z = zpre;
#pragma unroll
                for (int q = 0; q < 16; q++) z += sPS[(q * 16 + nlr) * 16 + br];
                sZ[nlr * 16 + br] = z;
            }
            __syncthreads();
            if (tid < 64) {
                float zi = sZ[jl * 16 + bb], zf = sZ[(4 + jl) * 16 + bb];
                float zg = sZ[(8 + jl) * 16 + bb], zo = sZ[(12 + jl) * 16 + bb];
                float si = 1.f / (1.f + expf(-zi)), sf = 1.f / (1.f + expf(-zf));
                float so = 1.f / (1.f + expf(-zo));
                creg = sf * creg + si * tanhf(zg);
                float hh = so * tanhf(creg);
                int j = c * 4 + jl;
                g_h[bb * 512 + j] = hh;
                g_ut[nx][(512 + j) * 16 + bb] = hh;
            }
            gbar(++gen);

            // ---------- phase 2a ----------
            {
                float* h_sh = sPS;
                h_sh[tid] = __ldcg(g_h + ab * 512 + tid);
                h_sh[tid + 256] = __ldcg(g_h + ab * 512 + tid + 256);
                __syncthreads();
                if (tid < 64) {
                    int s_l = tid >> 2, q = tid & 3;
                    const float4* kp = (const float4*)(sKeys + s_l * 512 + q * 128);
                    const float* hp = h_sh + q * 128;
                    float a = 0.f;
#pragma unroll 8
                    for (int i = 0; i < 32; i++) {
                        float4 kv = kp[i];
                        a += kv.x * hp[i * 4] + kv.y * hp[i * 4 + 1] +
                             kv.z * hp[i * 4 + 2] + kv.w * hp[i * 4 + 3];
                    }
                    a += __shfl_xor_sync(0xffffffffu, a, 1);
                    a += __shfl_xor_sync(0xffffffffu, a, 2);
                    if (q == 0) g_scores[ab * 128 + s0 + s_l] = a;
                }
            }
            gbar(++gen);

            // ---------- phase 2b ----------
            {
                float* w_sh = sPS + 512;
                float* red = sPS + 640;
                float* ctxp = sPS + 1024;
                if (tid < 128) w_sh[tid] = __ldcg(g_scores + ab * 128 + tid);
                __syncthreads();
                float sc = (tid < 128) ? w_sh[tid] : -1e30f;
                float mx = sc;
#pragma unroll
                for (int o = 16; o >= 1; o >>= 1)
                    mx = fmaxf(mx, __shfl_xor_sync(0xffffffffu, mx, o));
                if ((tid & 31) == 0) red[tid >> 5] = mx;
                __syncthreads();
                float gmx = fmaxf(fmaxf(red[0], red[1]), fmaxf(red[2], red[3]));
                __syncthreads();
                float e = (tid < 128) ? expf(sc - gmx) : 0.f;
                float smv = e;
#pragma unroll
                for (int o = 16; o >= 1; o >>= 1)
                    smv += __shfl_xor_sync(0xffffffffu, smv, o);
                if ((tid & 31) == 0) red[tid >> 5] = smv;
                __syncthreads();
                float gsum = red[0] + red[1] + red[2] + red[3];
                if (tid < 128) w_sh[tid] = e / gsum;
                __syncthreads();
                if (tid < 64) {
                    int sq = tid >> 4, d4l = tid & 15;
                    const float* mp = sMem + sq * 32 * 64;
                    float4 ca = make_float4(0.f, 0.f, 0.f, 0.f);
#pragma unroll 4
                    for (int i = 0; i < 32; i++) {
                        float w = w_sh[sq * 32 + i];
                        float4 mv = *(const float4*)(mp + i * 64 + d4l * 4);
                        ca.x += w * mv.x; ca.y += w * mv.y;
                        ca.z += w * mv.z; ca.w += w * mv.w;
                    }
                    *(float4*)&ctxp[sq * 64 + d4l * 4] = ca;
                }
                __syncthreads();
                if (tid < 64) {
                    float v = ctxp[tid] + ctxp[64 + tid] + ctxp[128 + tid] + ctxp[192 + tid];
                    g_ctxT[(d0 + tid) * 16 + ab] = v;
                }
            }
            gbar(++gen);

            // ---------- phase 3 ----------
            {
                const float4* hsrc = (const float4*)(g_ut[nx] + 512 * 16);
                const float4* csrc = (const float4*)g_ctxT;
                float4* du = (float4*)sU;
#pragma unroll
                for (int i = 0; i < 8; i++) du[tid + i * 256] = __ldcg(hsrc + tid + i * 256);
#pragma unroll
                for (int i = 0; i < 8; i++)
                    du[2048 + tid + i * 256] = __ldcg(csrc + tid + i * 256);
            }
            __syncthreads();
            {
                int b = tid & 15, kq = tid >> 4;
                const float* uc = sU + kq * 64 * 16 + b;
                const float4* wv = (const float4*)(sWa + kq * 64 * 4);
                float a0 = 0.f, a1 = 0.f, a2 = 0.f, a3 = 0.f;
#pragma unroll 4
                for (int i = 0; i < 64; i++) {
                    float u = uc[i * 16];
                    float4 w4 = wv[i];
                    a0 += u * w4.x; a1 += u * w4.y; a2 += u * w4.z; a3 += u * w4.w;
                }
                sPS[(kq * 4 + 0) * 16 + b] = a0;
                sPS[(kq * 4 + 1) * 16 + b] = a1;
                sPS[(kq * 4 + 2) * 16 + b] = a2;
                sPS[(kq * 4 + 3) * 16 + b] = a3;
            }
            __syncthreads();
            if (tid < 64) {
                int cl = tid >> 4, b2 = tid & 15;
                float v = 0.f;
#pragma unroll
                for (int q = 0; q < 16; q++) v += sPS[(q * 4 + cl) * 16 + b2];
                int col = c * 4 + cl;
                g_ut[nx][col * 16 + b2] = v;
                size_t row = (size_t)t * 16 + b2;
                g_Af16[row * 512 + col] = __float2half_rn(v);
            }
            gbar(++gen);
        }
    }

    // ================= vocab tile queue (all 148 CTAs) =================
    char* smb = (char*)(((uintptr_t)sm + 1023) & ~(uintptr_t)1023);
    uint32_t sbv = smem_u32(smb);
    for (;;) {
        __syncthreads();
        if (tid == 0) s_tile = atomicAdd(&g_vq, 1u);
        __syncthreads();
        unsigned i = s_tile;
        if (i >= 4000u) break;
        int yt = (int)(i / 250u), xt = (int)(i - (unsigned)yt * 250u);
        if (tid == 0) {
            unsigned need = (unsigned)(yt * 8 + 8);   // steps whose attns rows tile yt reads
            unsigned tgt = 512u * need, v;            // 4 bars/step * 128 CTA arrivals
            do {
                asm volatile("ld.acquire.gpu.u32 %0, [%1];" : "=r"(v) : "l"(&g_barc)
                             : "memory");
            } while (v < tgt);
        }
        __syncthreads();
        vocab_tile(smb, sbv, xt, yt, bf, out);
    }
}

extern "C" void kernel_launch(void* const* d_in, const int* in_sizes, int n_in,
                              void* d_out, int out_size) {
    const int* tokens = (const int*)d_in[0];
    const float* memory = (const float*)d_in[1];
    const float* h0 = (const float*)d_in[2];
    const float* c0 = (const float*)d_in[3];
    const float* emb = (const float*)d_in[4];
    const float* Wk = (const float*)d_in[5];
    const float* Wr = (const float*)d_in[6];
    const float* bvec = (const float*)d_in[7];
    const float* Wm = (const float*)d_in[8];
    const float* Wa = (const float*)d_in[9];
    const float* Wf = (const float*)d_in[10];
    const float* bf = (const float*)d_in[11];
    float* out = (float*)d_out;

    cudaFuncSetAttribute(fused_all, cudaFuncAttributeMaxDynamicSharedMemorySize, 231424);

    p0_init<<<32, 256>>>(h0);
    p4_bsplit<<<dim3(1000, 16), dim3(32, 8)>>>(Wf);
    sgemm_k<0><<<dim3(4, 16), 256>>>(memory, Wm, nullptr, nullptr, 512);
    sgemm_k<1><<<dim3(16, 16), 256>>>(emb, Wk, bvec, tokens, 256);

    fused_all<<<148, 256, 231424>>>(memory, Wk, Wr, Wa, c0, bf, out);
}